// round 10
// baseline (speedup 1.0000x reference)
#include <cuda_runtime.h>
#include <math.h>

#define NVOX 120000
#define EPSV 1e-5f

// ---------------- scratch (no dynamic alloc allowed) ----------------
__device__ __align__(16) float g_bufA[NVOX * 64];
__device__ __align__(16) float g_bufB[NVOX * 64];
__device__ __align__(16) float g_bufC[NVOX * 64];
__device__ __align__(16) float g_bufD[NVOX * 64];
__device__ __align__(16) float g_bufE[NVOX * 64];
__device__ float g_sum[7 * 64];
__device__ float g_sq [7 * 64];
// sort scratch (one per rulebook)
__device__ int g_permA[NVOX];
__device__ int g_permB[NVOX];
__device__ int g_maskA[NVOX];
__device__ int g_maskB[NVOX];
__device__ int g_histA[512];
__device__ int g_histB[512];

// ---------------- packed f32x2 helpers ----------------
__device__ __forceinline__ unsigned long long pack2same(float v) {
    unsigned long long r;
    asm("mov.b64 %0, {%1, %1};" : "=l"(r) : "f"(v));
    return r;
}
__device__ __forceinline__ unsigned long long pack2(float lo, float hi) {
    unsigned long long r;
    asm("mov.b64 %0, {%1, %2};" : "=l"(r) : "f"(lo), "f"(hi));
    return r;
}
__device__ __forceinline__ void unpack2(float& lo, float& hi, unsigned long long a) {
    asm("mov.b64 {%0, %1}, %2;" : "=f"(lo), "=f"(hi) : "l"(a));
}
__device__ __forceinline__ void ffma2(unsigned long long& d, unsigned long long a, unsigned long long b) {
    asm("fma.rn.f32x2 %0, %1, %2, %0;" : "+l"(d) : "l"(a), "l"(b));
}
__device__ __forceinline__ unsigned long long add2(unsigned long long a, unsigned long long b) {
    unsigned long long r;
    asm("add.rn.f32x2 %0, %1, %2;" : "=l"(r) : "l"(a), "l"(b));
    return r;
}
__device__ __forceinline__ unsigned long long mul2(unsigned long long a, unsigned long long b) {
    unsigned long long r;
    asm("mul.rn.f32x2 %0, %1, %2;" : "=l"(r) : "l"(a), "l"(b));
    return r;
}

template <int CT>
__device__ __forceinline__ void mac_row(unsigned long long* acc, float v, const float* w) {
    unsigned long long vv = pack2same(v);
    const ulonglong2* w2 = reinterpret_cast<const ulonglong2*>(w);
#pragma unroll
    for (int q = 0; q < CT / 4; q++) {
        ulonglong2 ww = w2[q];
        ffma2(acc[2 * q + 0], vv, ww.x);
        ffma2(acc[2 * q + 1], vv, ww.y);
    }
}

// ================= mask-bucket counting sort (both rulebooks, y-dim picks) ==
__global__ void mask_hist_kernel(const int* __restrict__ nbrA, const int* __restrict__ nbrB,
                                 int n, int* __restrict__ histA, int* __restrict__ histB,
                                 int* __restrict__ masksA, int* __restrict__ masksB) {
    const int* nbr   = blockIdx.y ? nbrB : nbrA;
    int* hist        = blockIdx.y ? histB : histA;
    int* masks       = blockIdx.y ? masksB : masksA;
    __shared__ int lh[512];
    for (int i = threadIdx.x; i < 512; i += blockDim.x) lh[i] = 0;
    __syncthreads();
    int r = blockIdx.x * blockDim.x + threadIdx.x;
    if (r < n) {
        const int* nb = nbr + (size_t)r * 9;
        int m = 0;
#pragma unroll
        for (int k = 0; k < 9; k++) m |= (nb[k] < n) << k;
        masks[r] = m;
        atomicAdd(&lh[m], 1);
    }
    __syncthreads();
    for (int i = threadIdx.x; i < 512; i += blockDim.x)
        if (lh[i]) atomicAdd(&hist[i], lh[i]);
}

__global__ void scan_kernel(int* __restrict__ histA, int* __restrict__ histB) {
    int* hist = blockIdx.x ? histB : histA;
    __shared__ int tmp[512];
    int t = threadIdx.x;
    tmp[t] = hist[t];
    __syncthreads();
    for (int off = 1; off < 512; off <<= 1) {
        int add = (t >= off) ? tmp[t - off] : 0;
        __syncthreads();
        tmp[t] += add;
        __syncthreads();
    }
    hist[t] = (t == 0) ? 0 : tmp[t - 1];
}

__global__ void scatter_kernel(const int* __restrict__ masksA, const int* __restrict__ masksB,
                               int n, int* __restrict__ offsA, int* __restrict__ offsB,
                               int* __restrict__ permA, int* __restrict__ permB) {
    const int* masks = blockIdx.y ? masksB : masksA;
    int* offs        = blockIdx.y ? offsB : offsA;
    int* perm        = blockIdx.y ? permB : permA;
    int r = blockIdx.x * blockDim.x + threadIdx.x;
    int lane = threadIdx.x & 31;
    int m = (r < n) ? masks[r] : -1;
    unsigned grp = __match_any_sync(0xffffffffu, m);
    int leader = __ffs(grp) - 1;
    int rank = __popc(grp & ((1u << lane) - 1u));
    int base = 0;
    if (lane == leader && m >= 0) base = atomicAdd(&offs[m], __popc(grp));
    base = __shfl_sync(0xffffffffu, base, leader);
    if (m >= 0) perm[base + rank] = r;
}

// ---------------- submanifold conv (persistent; fused BN-finalize + stats) --
// out = lrelu( sum_k gather_k(aff(in))@W_k ); rows via mask-sorted perm.
// AFFINE: compute scale/shift from previous stage's SUM/SQ + g,b in prologue.
// STATS: per-warp butterfly reduce lrelu outputs (+squares), REDG to osum/osq.
template <int CIN, int COUT, int CT, bool AFFINE, bool STATS>
__global__ void __launch_bounds__(256)
conv_kernel(const float* __restrict__ in, const int* __restrict__ nbr,
            const int* __restrict__ perm, const float* __restrict__ W,
            const float* __restrict__ psum, const float* __restrict__ psq,
            const float* __restrict__ g, const float* __restrict__ b,
            float* __restrict__ out, float* __restrict__ osum, float* __restrict__ osq,
            int n, int ntiles) {
    extern __shared__ __align__(16) float smem[];
    float* ws  = smem;                  // 9*CIN*CT
    float* csc = ws + 9 * CIN * CT;     // CIN
    float* csh = csc + CIN;             // CIN
    const int tid = threadIdx.x;
    const int lane = tid & 31;
    const int tb  = blockIdx.y * CT;

    // float4 weight staging: row r = (k*CIN+ci), take CT cols starting at tb
    {
        float4* ws4 = reinterpret_cast<float4*>(ws);
        const float4* W4 = reinterpret_cast<const float4*>(W);
        const int tb4 = tb >> 2;
        const int c4w = COUT >> 2;
        constexpr int TOT4 = 9 * CIN * CT / 4;
        constexpr int Q4 = CT / 4;
#pragma unroll 4
        for (int i = tid; i < TOT4; i += 256) {
            int r = i / Q4;
            int q = i - r * Q4;
            ws4[i] = W4[r * c4w + tb4 + q];
        }
    }
    if (AFFINE) {
        const float inv_n = 1.0f / (float)n;
        for (int i = tid; i < CIN; i += 256) {
            float m   = psum[i] * inv_n;
            float var = psq[i] * inv_n - m * m;   // biased variance
            float s   = g[i] / sqrtf(var + EPSV);
            csc[i] = s;
            csh[i] = b[i] - m * s;
        }
    }
    __syncthreads();

    for (int t = blockIdx.x; t < ntiles; t += gridDim.x) {
        const int gid = t * 256 + tid;
        const bool rok = gid < n;
        const int row = rok ? perm[gid] : 0;

        const int* nb = nbr + (size_t)row * 9;
        int idx[9];
#pragma unroll
        for (int k = 0; k < 9; k++) idx[k] = rok ? __ldg(nb + k) : n;

        unsigned long long acc[CT / 2];
#pragma unroll
        for (int i = 0; i < CT / 2; i++) acc[i] = 0ull;

#pragma unroll
        for (int k = 0; k < 9; k++) {
            const int j = idx[k];
            const bool v = j < n;
            if (!__any_sync(0xffffffffu, v)) continue;   // exact skip (mask-uniform warps)
            const float4* xr = reinterpret_cast<const float4*>(in + (size_t)j * CIN);
            const float* wk = ws + k * CIN * CT;
#pragma unroll
            for (int c4 = 0; c4 < CIN / 4; c4++) {
                float4 val = make_float4(0.f, 0.f, 0.f, 0.f);
                if (v) {
                    val = xr[c4];
                    if (AFFINE) {
                        val.x = fmaf(val.x, csc[4 * c4 + 0], csh[4 * c4 + 0]);
                        val.y = fmaf(val.y, csc[4 * c4 + 1], csh[4 * c4 + 1]);
                        val.z = fmaf(val.z, csc[4 * c4 + 2], csh[4 * c4 + 2]);
                        val.w = fmaf(val.w, csc[4 * c4 + 3], csh[4 * c4 + 3]);
                    }
                }
                const float* w0 = wk + (4 * c4) * CT;
                mac_row<CT>(acc, val.x, w0);
                mac_row<CT>(acc, val.y, w0 + CT);
                mac_row<CT>(acc, val.z, w0 + 2 * CT);
                mac_row<CT>(acc, val.w, w0 + 3 * CT);
            }
        }

        // leaky relu into acc (pack back), store valid rows
        float* o = out + (size_t)row * COUT + tb;
#pragma unroll
        for (int i = 0; i < CT / 2; i++) {
            float lo, hi;
            unpack2(lo, hi, acc[i]);
            lo = lo > 0.f ? lo : 0.01f * lo;
            hi = hi > 0.f ? hi : 0.01f * hi;
            acc[i] = pack2(lo, hi);
            if (rok) reinterpret_cast<float2*>(o)[i] = make_float2(lo, hi);
        }

        if (STATS) {
            // per-warp butterfly over rows; invalid lanes hold zeros
#pragma unroll
            for (int i = 0; i < CT / 2; i++) {
                unsigned long long v = acc[i];
                unsigned long long q = mul2(v, v);
#pragma unroll
                for (int m = 16; m; m >>= 1) {
                    v = add2(v, __shfl_xor_sync(0xffffffffu, v, m));
                    q = add2(q, __shfl_xor_sync(0xffffffffu, q, m));
                }
                if (lane == i) {
                    float lo, hi;
                    unpack2(lo, hi, v);
                    atomicAdd(osum + tb + 2 * i, lo);
                    atomicAdd(osum + tb + 2 * i + 1, hi);
                }
                if (lane == 16 + i) {
                    float lo, hi;
                    unpack2(lo, hi, q);
                    atomicAdd(osq + tb + 2 * i, lo);
                    atomicAdd(osq + tb + 2 * i + 1, hi);
                }
            }
        }
    }
}

// ---------------- out = bnA(a) + bnB(b); bn params computed in prologue -----
template <int C>
__global__ void combine_kernel(const float* __restrict__ a,
                               const float* __restrict__ suma, const float* __restrict__ sqa,
                               const float* __restrict__ ga, const float* __restrict__ ba,
                               const float* __restrict__ bsrc,
                               const float* __restrict__ sumb, const float* __restrict__ sqb,
                               const float* __restrict__ gb, const float* __restrict__ bb,
                               float* __restrict__ o, int n) {
    __shared__ float sA[C], hA[C], sB[C], hB[C];
    const float inv_n = 1.0f / (float)n;
    for (int i = threadIdx.x; i < C; i += blockDim.x) {
        float m   = suma[i] * inv_n;
        float var = sqa[i] * inv_n - m * m;
        float s   = ga[i] / sqrtf(var + EPSV);
        sA[i] = s; hA[i] = ba[i] - m * s;
        m   = sumb[i] * inv_n;
        var = sqb[i] * inv_n - m * m;
        s   = gb[i] / sqrtf(var + EPSV);
        sB[i] = s; hB[i] = bb[i] - m * s;
    }
    __syncthreads();
    const int total = n * C;
    for (int i = blockIdx.x * blockDim.x + threadIdx.x; i < total; i += gridDim.x * blockDim.x) {
        int c = i & (C - 1);
        o[i] = fmaf(a[i], sA[c], hA[c]) + fmaf(bsrc[i], sB[c], hB[c]);
    }
}

__global__ void zero_kernel(float* __restrict__ sum, float* __restrict__ sq,
                            int* __restrict__ hA, int* __restrict__ hB) {
    int i = blockIdx.x * blockDim.x + threadIdx.x;
    if (i < 7 * 64) { sum[i] = 0.f; sq[i] = 0.f; }
    if (i < 512) { hA[i] = 0; hB[i] = 0; }
}

// ---------------- host launch sequence ----------------
static constexpr size_t smem_for(int cin, int ct) {
    return (size_t)(9 * cin * ct + 2 * cin) * sizeof(float);
}

template <int CIN, int COUT, int CT, bool AFFINE, bool STATS>
static int pgrid(int ntiles, int div) {
    static int occ = -1;
    if (occ < 0) {
        cudaFuncSetAttribute((const void*)conv_kernel<CIN, COUT, CT, AFFINE, STATS>,
                             cudaFuncAttributeMaxDynamicSharedMemorySize, (int)smem_for(CIN, CT));
        cudaOccupancyMaxActiveBlocksPerMultiprocessor(&occ, conv_kernel<CIN, COUT, CT, AFFINE, STATS>,
                                                      256, smem_for(CIN, CT));
        if (occ < 1) occ = 1;
    }
    int gx = (occ * 148) / div;
    if (gx < 1) gx = 1;
    if (gx > ntiles) gx = ntiles;
    return gx;
}

extern "C" void kernel_launch(void* const* d_in, const int* in_sizes, int n_in,
                              void* d_out, int out_size) {
    const float* x      = (const float*)d_in[0];
    const int*   nbr133 = (const int*)  d_in[1];
    const int*   nbr313 = (const int*)  d_in[2];
    const float* W_c1   = (const float*)d_in[3];
    const float* g0     = (const float*)d_in[4];
    const float* b0     = (const float*)d_in[5];
    const float* W_c12  = (const float*)d_in[6];
    const float* g02    = (const float*)d_in[7];
    const float* b02    = (const float*)d_in[8];
    const float* W_c2   = (const float*)d_in[9];
    const float* W_c3   = (const float*)d_in[10];
    const float* g2     = (const float*)d_in[11];
    const float* b2     = (const float*)d_in[12];
    const float* W_r1   = (const float*)d_in[13];
    const float* rg0    = (const float*)d_in[14];
    const float* rb0    = (const float*)d_in[15];
    const float* W_r12  = (const float*)d_in[16];
    const float* rg02   = (const float*)d_in[17];
    const float* rb02   = (const float*)d_in[18];
    const float* W_r2   = (const float*)d_in[19];
    const float* rg1    = (const float*)d_in[20];
    const float* rb1    = (const float*)d_in[21];
    const float* W_r3   = (const float*)d_in[22];
    const float* rg2    = (const float*)d_in[23];
    const float* rb2    = (const float*)d_in[24];
    float* out = (float*)d_out;

    const int n = in_sizes[0] / 16;   // 120000

    float *BA, *BB, *BC, *BD, *BE, *SUM, *SQ;
    int *PA, *PB, *MA, *MB, *HA, *HB;
    cudaGetSymbolAddress((void**)&BA,  g_bufA);
    cudaGetSymbolAddress((void**)&BB,  g_bufB);
    cudaGetSymbolAddress((void**)&BC,  g_bufC);
    cudaGetSymbolAddress((void**)&BD,  g_bufD);
    cudaGetSymbolAddress((void**)&BE,  g_bufE);
    cudaGetSymbolAddress((void**)&SUM, g_sum);
    cudaGetSymbolAddress((void**)&SQ,  g_sq);
    cudaGetSymbolAddress((void**)&PA,  g_permA);
    cudaGetSymbolAddress((void**)&PB,  g_permB);
    cudaGetSymbolAddress((void**)&MA,  g_maskA);
    cudaGetSymbolAddress((void**)&MB,  g_maskB);
    cudaGetSymbolAddress((void**)&HA,  g_histA);
    cudaGetSymbolAddress((void**)&HB,  g_histB);

    // streams/events for branch parallelism (created outside capture on call 1)
    static cudaStream_t s1 = 0, s2 = 0;
    static cudaEvent_t ev[6];
    if (!s1) {
        cudaStreamCreateWithFlags(&s1, cudaStreamNonBlocking);
        cudaStreamCreateWithFlags(&s2, cudaStreamNonBlocking);
        for (int i = 0; i < 6; i++) cudaEventCreateWithFlags(&ev[i], cudaEventDisableTiming);
    }

    const int TB = 256;
    const int ntiles = (n + TB - 1) / TB;
    const int G = ntiles;

    const int g1632  = pgrid<16, 32, 32, false, true >(ntiles, 2);
    const int g1632n = pgrid<16, 32, 32, false, false>(ntiles, 2);
    const int g3232t = pgrid<32, 32, 32, true,  true >(ntiles, 2);
    const int g3232f = pgrid<32, 32, 32, false, true >(ntiles, 2);
    const int g3264  = pgrid<32, 64, 32, false, true >(ntiles, 2);
    const int g6464  = pgrid<64, 64, 32, true,  true >(ntiles, 2);

    // ----- prologue (null stream): zero + mask-bucket sort of both rulebooks -----
    zero_kernel<<<2, 512>>>(SUM, SQ, HA, HB);
    mask_hist_kernel<<<dim3(G, 2), TB>>>(nbr133, nbr313, n, HA, HB, MA, MB);
    scan_kernel<<<2, 512>>>(HA, HB);
    scatter_kernel<<<dim3(G, 2), TB>>>(MA, MB, n, HA, HB, PA, PB);

    // ===== ResContextBlock (16 -> 32): s-chain on s1, r-chain on s2 =====
    cudaEventRecord(ev[0], 0);
    cudaStreamWaitEvent(s1, ev[0], 0);
    cudaStreamWaitEvent(s2, ev[0], 0);

    // s1: c1 -> c12
    conv_kernel<16, 32, 32, false, true><<<dim3(g1632, 1), TB, smem_for(16, 32), s1>>>(
        x, nbr133, PA, W_c1, nullptr, nullptr, nullptr, nullptr, BA, SUM + 0, SQ + 0, n, ntiles);
    conv_kernel<32, 32, 32, true, true><<<dim3(g3232t, 1), TB, smem_for(32, 32), s1>>>(
        BA, nbr313, PB, W_c12, SUM + 0, SQ + 0, g0, b0, BB, SUM + 64, SQ + 64, n, ntiles);
    // s2: c2 -> c3
    conv_kernel<16, 32, 32, false, false><<<dim3(g1632n, 1), TB, smem_for(16, 32), s2>>>(
        x, nbr313, PB, W_c2, nullptr, nullptr, nullptr, nullptr, BC, nullptr, nullptr, n, ntiles);
    conv_kernel<32, 32, 32, false, true><<<dim3(g3232f, 1), TB, smem_for(32, 32), s2>>>(
        BC, nbr133, PA, W_c3, nullptr, nullptr, nullptr, nullptr, BD, SUM + 128, SQ + 128, n, ntiles);

    cudaEventRecord(ev[1], s1);
    cudaEventRecord(ev[2], s2);
    cudaStreamWaitEvent(0, ev[1], 0);
    cudaStreamWaitEvent(0, ev[2], 0);

    // y = bn2(BD) + bn1(BB) -> BC
    combine_kernel<32><<<592, 256>>>(BD, SUM + 128, SQ + 128, g2, b2,
                                     BB, SUM + 64,  SQ + 64,  g02, b02, BC, n);

    // ===== ResBlock (32 -> 64): s2-chain on s1, r2-chain on s2 =====
    cudaEventRecord(ev[3], 0);
    cudaStreamWaitEvent(s1, ev[3], 0);
    cudaStreamWaitEvent(s2, ev[3], 0);

    // s1: r1 -> r12
    conv_kernel<32, 64, 32, false, true><<<dim3(g3264, 2), TB, smem_for(32, 32), s1>>>(
        BC, nbr313, PB, W_r1, nullptr, nullptr, nullptr, nullptr, BA, SUM + 192, SQ + 192, n, ntiles);
    conv_kernel<64, 64, 32, true, true><<<dim3(g6464, 2), TB, smem_for(64, 32), s1>>>(
        BA, nbr133, PA, W_r12, SUM + 192, SQ + 192, rg0, rb0, BB, SUM + 256, SQ + 256, n, ntiles);
    // s2: r2 -> r3
    conv_kernel<32, 64, 32, false, true><<<dim3(g3264, 2), TB, smem_for(32, 32), s2>>>(
        BC, nbr133, PA, W_r2, nullptr, nullptr, nullptr, nullptr, BD, SUM + 320, SQ + 320, n, ntiles);
    conv_kernel<64, 64, 32, true, true><<<dim3(g6464, 2), TB, smem_for(64, 32), s2>>>(
        BD, nbr313, PB, W_r3, SUM + 320, SQ + 320, rg1, rb1, BE, SUM + 384, SQ + 384, n, ntiles);

    cudaEventRecord(ev[4], s1);
    cudaEventRecord(ev[5], s2);
    cudaStreamWaitEvent(0, ev[4], 0);
    cudaStreamWaitEvent(0, ev[5], 0);

    // out = bn6(BE) + bn4(BB)
    combine_kernel<64><<<1184, 256>>>(BE, SUM + 384, SQ + 384, rg2, rb2,
                                      BB, SUM + 256, SQ + 256, rg02, rb02, out, n);
}

// round 11
// speedup vs baseline: 1.8602x; 1.8602x over previous
#include <cuda_runtime.h>
#include <math.h>

#define NVOX 120000
#define EPSV 1e-5f

// ---------------- scratch (no dynamic alloc allowed) ----------------
__device__ __align__(16) float g_bufA[NVOX * 64];
__device__ __align__(16) float g_bufB[NVOX * 64];
__device__ __align__(16) float g_bufC[NVOX * 64];
__device__ __align__(16) float g_bufD[NVOX * 64];
__device__ __align__(16) float g_bufE[NVOX * 64];
__device__ float g_sum[7 * 64];
__device__ float g_sq [7 * 64];
__device__ float g_sc [7 * 64];
__device__ float g_sh [7 * 64];
__device__ int   g_ctr[8];
__device__ int g_permA[NVOX];
__device__ int g_permB[NVOX];
__device__ int g_maskA[NVOX];
__device__ int g_maskB[NVOX];
__device__ int g_histA[512];
__device__ int g_histB[512];

// ---------------- packed f32x2 helpers ----------------
__device__ __forceinline__ unsigned long long pack2same(float v) {
    unsigned long long r;
    asm("mov.b64 %0, {%1, %1};" : "=l"(r) : "f"(v));
    return r;
}
__device__ __forceinline__ void unpack2(float& lo, float& hi, unsigned long long a) {
    asm("mov.b64 {%0, %1}, %2;" : "=f"(lo), "=f"(hi) : "l"(a));
}
__device__ __forceinline__ void ffma2(unsigned long long& d, unsigned long long a, unsigned long long b) {
    asm("fma.rn.f32x2 %0, %1, %2, %0;" : "+l"(d) : "l"(a), "l"(b));
}

template <int CT>
__device__ __forceinline__ void mac_row(unsigned long long* acc, float v, const float* w) {
    unsigned long long vv = pack2same(v);
    const ulonglong2* w2 = reinterpret_cast<const ulonglong2*>(w);
#pragma unroll
    for (int q = 0; q < CT / 4; q++) {
        ulonglong2 ww = w2[q];
        ffma2(acc[2 * q + 0], vv, ww.x);
        ffma2(acc[2 * q + 1], vv, ww.y);
    }
}

__device__ __forceinline__ float lrelu(float x) { return x > 0.f ? x : 0.01f * x; }

__device__ __forceinline__ float to_tf32(float x) {
    float r;
    asm("cvt.rna.tf32.f32 %0, %1;" : "=f"(r) : "f"(x));
    return r;
}

__device__ __forceinline__ void mma_tf32(float* c, const unsigned* a, unsigned b0, unsigned b1) {
    asm("mma.sync.aligned.m16n8k8.row.col.f32.tf32.tf32.f32 "
        "{%0,%1,%2,%3}, {%4,%5,%6,%7}, {%8,%9}, {%0,%1,%2,%3};"
        : "+f"(c[0]), "+f"(c[1]), "+f"(c[2]), "+f"(c[3])
        : "r"(a[0]), "r"(a[1]), "r"(a[2]), "r"(a[3]), "r"(b0), "r"(b1));
}

// ================= mask-bucket counting sort (both rulebooks) ==============
__global__ void mask_hist_kernel(const int* __restrict__ nbrA, const int* __restrict__ nbrB,
                                 int n, int* __restrict__ histA, int* __restrict__ histB,
                                 int* __restrict__ masksA, int* __restrict__ masksB) {
    const int* nbr = blockIdx.y ? nbrB : nbrA;
    int* hist      = blockIdx.y ? histB : histA;
    int* masks     = blockIdx.y ? masksB : masksA;
    __shared__ int lh[512];
    for (int i = threadIdx.x; i < 512; i += blockDim.x) lh[i] = 0;
    __syncthreads();
    int r = blockIdx.x * blockDim.x + threadIdx.x;
    if (r < n) {
        const int* nb = nbr + (size_t)r * 9;
        int m = 0;
#pragma unroll
        for (int k = 0; k < 9; k++) m |= (nb[k] < n) << k;
        masks[r] = m;
        atomicAdd(&lh[m], 1);
    }
    __syncthreads();
    for (int i = threadIdx.x; i < 512; i += blockDim.x)
        if (lh[i]) atomicAdd(&hist[i], lh[i]);
}

__global__ void scan_kernel(int* __restrict__ histA, int* __restrict__ histB) {
    int* hist = blockIdx.x ? histB : histA;
    __shared__ int tmp[512];
    int t = threadIdx.x;
    tmp[t] = hist[t];
    __syncthreads();
    for (int off = 1; off < 512; off <<= 1) {
        int add = (t >= off) ? tmp[t - off] : 0;
        __syncthreads();
        tmp[t] += add;
        __syncthreads();
    }
    hist[t] = (t == 0) ? 0 : tmp[t - 1];
}

// after scatter, hist[m] = END offset of bucket m; min mask = 16 (center bit),
// so hist[16] = count of center-only rows = dense/sparse boundary.
__global__ void scatter_kernel(const int* __restrict__ masksA, const int* __restrict__ masksB,
                               int n, int* __restrict__ offsA, int* __restrict__ offsB,
                               int* __restrict__ permA, int* __restrict__ permB) {
    const int* masks = blockIdx.y ? masksB : masksA;
    int* offs        = blockIdx.y ? offsB : offsA;
    int* perm        = blockIdx.y ? permB : permA;
    int r = blockIdx.x * blockDim.x + threadIdx.x;
    int lane = threadIdx.x & 31;
    int m = (r < n) ? masks[r] : -1;
    unsigned grp = __match_any_sync(0xffffffffu, m);
    int leader = __ffs(grp) - 1;
    int rank = __popc(grp & ((1u << lane) - 1u));
    int base = 0;
    if (lane == leader && m >= 0) base = atomicAdd(&offs[m], __popc(grp));
    base = __shfl_sync(0xffffffffu, base, leader);
    if (m >= 0) perm[base + rank] = r;
}

// ============ dense-center GEMM on tensor pipe (tf32 mma.sync) =============
// Handles rows perm[0 .. hist[16]) — center-only rows: out = lrelu(aff(x) @ Wc).
// Per warp: 16-row strip; A staged via gather into padded smem (tf32-converted,
// affine folded), fragments per PTX m16n8k8 layout; C restaged to smem and
// scatter-stored as float4 with lrelu.
template <int CIN, int COUT, bool AFFINE>
__global__ void __launch_bounds__(256)
gemm_center_kernel(const float* __restrict__ in, const int* __restrict__ perm,
                   const int* __restrict__ hist, const float* __restrict__ W,
                   const float* __restrict__ sc, const float* __restrict__ sh,
                   float* __restrict__ out) {
    constexpr int MX = (CIN > COUT) ? CIN : COUT;
    constexpr int SP = MX + 4;          // padded stage row (float4-aligned, conflict-light)
    constexpr int WP = COUT + 1;        // padded W row
    extern __shared__ __align__(16) float sm[];
    float* wsm = sm;                    // CIN*WP (tf32 bit patterns)
    float* stg = wsm + CIN * WP;        // 8 warps * 16 * SP
    float* csc = stg + 8 * 16 * SP;     // CIN
    float* csh = csc + CIN;             // CIN
    const int tid = threadIdx.x, wid = tid >> 5, lane = tid & 31;
    const int gr = lane >> 2, tg = lane & 3;

    if (AFFINE) {
        const float inv_keep = 1.0f;  (void)inv_keep;
        for (int i = tid; i < CIN; i += 256) { csc[i] = sc[i]; csh[i] = sh[i]; }
    }
    {   // stage center weight slice (k=4), tf32-converted
        const float* Wc = W + 4 * CIN * COUT;
        for (int i = tid; i < CIN * COUT; i += 256) {
            int k = i / COUT, nn = i - k * COUT;
            wsm[k * WP + nn] = to_tf32(Wc[i]);
        }
    }
    __syncthreads();
    const int B16 = __ldg(hist + 16);
    float* aw = stg + wid * 16 * SP;

    for (int base = blockIdx.x * 128; base < B16; base += gridDim.x * 128) {
        const int wbase = base + wid * 16;
        if (wbase >= B16) continue;                // warp-private; no block sync in loop
        __syncwarp();
        int prow = -1;
        if (lane < 16 && wbase + lane < B16) prow = perm[wbase + lane];

        // stage A: 16 rows x CIN (affine + tf32), float4 gather
#pragma unroll
        for (int it = 0; it < CIN / 8; it++) {
            int e = it * 32 + lane;
            int r = e / (CIN / 4), c4 = e - r * (CIN / 4);
            int pr = __shfl_sync(0xffffffffu, prow, r);
            float4 v = make_float4(0.f, 0.f, 0.f, 0.f);
            if (pr >= 0) {
                v = *reinterpret_cast<const float4*>(in + (size_t)pr * CIN + 4 * c4);
                if (AFFINE) {
                    v.x = fmaf(v.x, csc[4 * c4 + 0], csh[4 * c4 + 0]);
                    v.y = fmaf(v.y, csc[4 * c4 + 1], csh[4 * c4 + 1]);
                    v.z = fmaf(v.z, csc[4 * c4 + 2], csh[4 * c4 + 2]);
                    v.w = fmaf(v.w, csc[4 * c4 + 3], csh[4 * c4 + 3]);
                }
            }
            v.x = to_tf32(v.x); v.y = to_tf32(v.y); v.z = to_tf32(v.z); v.w = to_tf32(v.w);
            *reinterpret_cast<float4*>(aw + r * SP + 4 * c4) = v;
        }
        __syncwarp();

        // A fragments (m16n8k8 row-major layout)
        unsigned af[CIN / 8][4];
#pragma unroll
        for (int kt = 0; kt < CIN / 8; kt++) {
            const float* r0 = aw + gr * SP + kt * 8 + tg;
            const float* r1 = aw + (gr + 8) * SP + kt * 8 + tg;
            af[kt][0] = __float_as_uint(r0[0]);
            af[kt][1] = __float_as_uint(r1[0]);
            af[kt][2] = __float_as_uint(r0[4]);
            af[kt][3] = __float_as_uint(r1[4]);
        }

        float cf[COUT / 8][4];
#pragma unroll
        for (int nt = 0; nt < COUT / 8; nt++) {
            cf[nt][0] = cf[nt][1] = cf[nt][2] = cf[nt][3] = 0.f;
#pragma unroll
            for (int kt = 0; kt < CIN / 8; kt++) {
                unsigned b0 = __float_as_uint(wsm[(kt * 8 + tg) * WP + nt * 8 + gr]);
                unsigned b1 = __float_as_uint(wsm[(kt * 8 + tg + 4) * WP + nt * 8 + gr]);
                mma_tf32(cf[nt], af[kt], b0, b1);
            }
        }
        __syncwarp();

        // C -> smem with lrelu (C layout: rows gr/gr+8, cols 2*tg, 2*tg+1 per n-tile)
#pragma unroll
        for (int nt = 0; nt < COUT / 8; nt++) {
            int col = nt * 8 + 2 * tg;
            aw[gr * SP + col]           = lrelu(cf[nt][0]);
            aw[gr * SP + col + 1]       = lrelu(cf[nt][1]);
            aw[(gr + 8) * SP + col]     = lrelu(cf[nt][2]);
            aw[(gr + 8) * SP + col + 1] = lrelu(cf[nt][3]);
        }
        __syncwarp();

        // scatter-store float4
#pragma unroll
        for (int it = 0; it < COUT / 8; it++) {
            int e = it * 32 + lane;
            int r = e / (COUT / 4), c4 = e - r * (COUT / 4);
            int pr = __shfl_sync(0xffffffffu, prow, r);
            if (pr >= 0)
                *reinterpret_cast<float4*>(out + (size_t)pr * COUT + 4 * c4) =
                    *reinterpret_cast<const float4*>(aw + r * SP + 4 * c4);
        }
    }
}

// ---------------- sparse conv: rows perm[hist[16] .. n) — full fp32 path ----
template <int CIN, int COUT, int CT, bool AFFINE>
__global__ void __launch_bounds__(256)
conv_sparse_kernel(const float* __restrict__ in, const int* __restrict__ nbr,
                   const int* __restrict__ perm, const int* __restrict__ hist,
                   const float* __restrict__ W,
                   const float* __restrict__ sc, const float* __restrict__ sh,
                   float* __restrict__ out, int n, int ntiles) {
    extern __shared__ __align__(16) float smem[];
    float* ws  = smem;                  // 9*CIN*CT
    float* csc = ws + 9 * CIN * CT;     // CIN
    float* csh = csc + CIN;             // CIN
    const int tid = threadIdx.x;
    const int tb  = blockIdx.y * CT;

    {
        float4* ws4 = reinterpret_cast<float4*>(ws);
        const float4* W4 = reinterpret_cast<const float4*>(W);
        const int tb4 = tb >> 2;
        const int c4w = COUT >> 2;
        constexpr int TOT4 = 9 * CIN * CT / 4;
        constexpr int Q4 = CT / 4;
#pragma unroll 4
        for (int i = tid; i < TOT4; i += 256) {
            int r = i / Q4;
            int q = i - r * Q4;
            ws4[i] = W4[r * c4w + tb4 + q];
        }
    }
    if (AFFINE) {
        for (int i = tid; i < CIN; i += 256) { csc[i] = sc[i]; csh[i] = sh[i]; }
    }
    __syncthreads();

    const int B16 = __ldg(hist + 16);
    const int t0 = B16 >> 8;

    for (int t = t0 + blockIdx.x; t < ntiles; t += gridDim.x) {
        const int gid = t * 256 + tid;
        const bool rok = (gid < n) && (gid >= B16);
        const int row = rok ? perm[gid] : 0;

        const int* nb = nbr + (size_t)row * 9;
        int idx[9];
#pragma unroll
        for (int k = 0; k < 9; k++) idx[k] = rok ? __ldg(nb + k) : n;

        unsigned long long acc[CT / 2];
#pragma unroll
        for (int i = 0; i < CT / 2; i++) acc[i] = 0ull;

#pragma unroll
        for (int k = 0; k < 9; k++) {
            const int j = idx[k];
            const bool v = j < n;
            if (!__any_sync(0xffffffffu, v)) continue;
            const float4* xr = reinterpret_cast<const float4*>(in + (size_t)j * CIN);
            const float* wk = ws + k * CIN * CT;
#pragma unroll
            for (int c4 = 0; c4 < CIN / 4; c4++) {
                float4 val = make_float4(0.f, 0.f, 0.f, 0.f);
                if (v) {
                    val = xr[c4];
                    if (AFFINE) {
                        val.x = fmaf(val.x, csc[4 * c4 + 0], csh[4 * c4 + 0]);
                        val.y = fmaf(val.y, csc[4 * c4 + 1], csh[4 * c4 + 1]);
                        val.z = fmaf(val.z, csc[4 * c4 + 2], csh[4 * c4 + 2]);
                        val.w = fmaf(val.w, csc[4 * c4 + 3], csh[4 * c4 + 3]);
                    }
                }
                const float* w0 = wk + (4 * c4) * CT;
                mac_row<CT>(acc, val.x, w0);
                mac_row<CT>(acc, val.y, w0 + CT);
                mac_row<CT>(acc, val.z, w0 + 2 * CT);
                mac_row<CT>(acc, val.w, w0 + 3 * CT);
            }
        }

        if (rok) {
            float* o = out + (size_t)row * COUT + tb;
#pragma unroll
            for (int i = 0; i < CT / 2; i++) {
                float lo, hi;
                unpack2(lo, hi, acc[i]);
                reinterpret_cast<float2*>(o)[i] = make_float2(lrelu(lo), lrelu(hi));
            }
        }
    }
}

// ---------------- per-channel sum/sumsq + last-block BN finalize ------------
template <int C>
__global__ void statsbn_kernel(const float* __restrict__ d, int n,
                               float* __restrict__ sum, float* __restrict__ sq,
                               const float* __restrict__ g, const float* __restrict__ b,
                               float* __restrict__ scale, float* __restrict__ shift,
                               int* __restrict__ ctr) {
    __shared__ float ss[512];
    __shared__ float qq[512];
    __shared__ int last;
    const int tid = threadIdx.x;
    const int col = tid % C;
    const int rl  = tid / C;
    const int rpb = blockDim.x / C;
    float s = 0.f, q = 0.f;
    for (int r = blockIdx.x * rpb + rl; r < n; r += gridDim.x * rpb) {
        float v = d[(size_t)r * C + col];
        s += v; q += v * v;
    }
    ss[tid] = s; qq[tid] = q;
    __syncthreads();
    for (int off = blockDim.x / 2; off >= C; off >>= 1) {
        if (tid < off) { ss[tid] += ss[tid + off]; qq[tid] += qq[tid + off]; }
        __syncthreads();
    }
    if (tid < C) {
        atomicAdd(sum + tid, ss[tid]);
        atomicAdd(sq + tid, qq[tid]);
    }
    __threadfence();
    __syncthreads();
    if (tid == 0) last = (atomicAdd(ctr, 1) == (int)gridDim.x - 1);
    __syncthreads();
    if (last && tid < C) {
        float inv_n = 1.0f / (float)n;
        float m   = __ldcg(sum + tid) * inv_n;
        float var = __ldcg(sq + tid) * inv_n - m * m;   // biased variance
        float sc2 = g[tid] / sqrtf(var + EPSV);
        scale[tid] = sc2;
        shift[tid] = b[tid] - m * sc2;
    }
}

// ---------------- out = aff(a) + aff(b) ----------------
template <int C>
__global__ void combine_kernel(const float* __restrict__ a, const float* __restrict__ sa, const float* __restrict__ ha,
                               const float* __restrict__ b, const float* __restrict__ sb, const float* __restrict__ hb,
                               float* __restrict__ o, int total) {
    int i = blockIdx.x * blockDim.x + threadIdx.x;
    if (i >= total) return;
    int c = i & (C - 1);
    o[i] = fmaf(a[i], sa[c], ha[c]) + fmaf(b[i], sb[c], hb[c]);
}

__global__ void zero_kernel(float* __restrict__ sum, float* __restrict__ sq,
                            int* __restrict__ hA, int* __restrict__ hB,
                            int* __restrict__ ctr) {
    int i = blockIdx.x * blockDim.x + threadIdx.x;
    if (i < 7 * 64) { sum[i] = 0.f; sq[i] = 0.f; }
    if (i < 512) { hA[i] = 0; hB[i] = 0; }
    if (i < 8) ctr[i] = 0;
}

// ---------------- host ----------------
static constexpr size_t smem_sparse(int cin, int ct) {
    return (size_t)(9 * cin * ct + 2 * cin) * sizeof(float);
}
static constexpr size_t smem_gemm(int cin, int cout) {
    int mx = cin > cout ? cin : cout;
    return (size_t)(cin * (cout + 1) + 8 * 16 * (mx + 4) + 2 * cin) * sizeof(float);
}

extern "C" void kernel_launch(void* const* d_in, const int* in_sizes, int n_in,
                              void* d_out, int out_size) {
    const float* x      = (const float*)d_in[0];
    const int*   nbr133 = (const int*)  d_in[1];
    const int*   nbr313 = (const int*)  d_in[2];
    const float* W_c1   = (const float*)d_in[3];
    const float* g0     = (const float*)d_in[4];
    const float* b0     = (const float*)d_in[5];
    const float* W_c12  = (const float*)d_in[6];
    const float* g02    = (const float*)d_in[7];
    const float* b02    = (const float*)d_in[8];
    const float* W_c2   = (const float*)d_in[9];
    const float* W_c3   = (const float*)d_in[10];
    const float* g2     = (const float*)d_in[11];
    const float* b2     = (const float*)d_in[12];
    const float* W_r1   = (const float*)d_in[13];
    const float* rg0    = (const float*)d_in[14];
    const float* rb0    = (const float*)d_in[15];
    const float* W_r12  = (const float*)d_in[16];
    const float* rg02   = (const float*)d_in[17];
    const float* rb02   = (const float*)d_in[18];
    const float* W_r2   = (const float*)d_in[19];
    const float* rg1    = (const float*)d_in[20];
    const float* rb1    = (const float*)d_in[21];
    const float* W_r3   = (const float*)d_in[22];
    const float* rg2    = (const float*)d_in[23];
    const float* rb2    = (const float*)d_in[24];
    float* out = (float*)d_out;

    const int n = in_sizes[0] / 16;   // 120000

    float *BA, *BB, *BC, *BD, *BE, *SUM, *SQ, *SC, *SH;
    int *PA, *PB, *MA, *MB, *HA, *HB, *CTR;
    cudaGetSymbolAddress((void**)&BA,  g_bufA);
    cudaGetSymbolAddress((void**)&BB,  g_bufB);
    cudaGetSymbolAddress((void**)&BC,  g_bufC);
    cudaGetSymbolAddress((void**)&BD,  g_bufD);
    cudaGetSymbolAddress((void**)&BE,  g_bufE);
    cudaGetSymbolAddress((void**)&SUM, g_sum);
    cudaGetSymbolAddress((void**)&SQ,  g_sq);
    cudaGetSymbolAddress((void**)&SC,  g_sc);
    cudaGetSymbolAddress((void**)&SH,  g_sh);
    cudaGetSymbolAddress((void**)&PA,  g_permA);
    cudaGetSymbolAddress((void**)&PB,  g_permB);
    cudaGetSymbolAddress((void**)&MA,  g_maskA);
    cudaGetSymbolAddress((void**)&MB,  g_maskB);
    cudaGetSymbolAddress((void**)&HA,  g_histA);
    cudaGetSymbolAddress((void**)&HB,  g_histB);
    cudaGetSymbolAddress((void**)&CTR, g_ctr);

    static int inited = 0;
    if (!inited) {
        inited = 1;
        cudaFuncSetAttribute((const void*)gemm_center_kernel<64, 64, true>,
                             cudaFuncAttributeMaxDynamicSharedMemorySize, (int)smem_gemm(64, 64));
        cudaFuncSetAttribute((const void*)gemm_center_kernel<32, 64, false>,
                             cudaFuncAttributeMaxDynamicSharedMemorySize, (int)smem_gemm(32, 64));
    }

    const int TB = 256;
    const int ntiles = (n + TB - 1) / TB;
    const int G = ntiles;
    const int GG = 296;              // gemm grid (persistent, 2/SM)
    const int SG = 128;              // sparse grid.x (~tiles in sparse region)

    // ----- prologue -----
    zero_kernel<<<2, 512>>>(SUM, SQ, HA, HB, CTR);
    mask_hist_kernel<<<dim3(G, 2), TB>>>(nbr133, nbr313, n, HA, HB, MA, MB);
    scan_kernel<<<2, 512>>>(HA, HB);
    scatter_kernel<<<dim3(G, 2), TB>>>(MA, MB, n, HA, HB, PA, PB);

    // ===== ResContextBlock (16 -> 32) =====
    gemm_center_kernel<16, 32, false><<<GG, TB, smem_gemm(16, 32)>>>(x, PA, HA, W_c1, nullptr, nullptr, BA);
    conv_sparse_kernel<16, 32, 16, false><<<dim3(SG, 2), TB, smem_sparse(16, 16)>>>(x, nbr133, PA, HA, W_c1, nullptr, nullptr, BA, n, ntiles);
    statsbn_kernel<32><<<148, 512>>>(BA, n, SUM + 0, SQ + 0, g0, b0, SC + 0, SH + 0, CTR + 0);

    gemm_center_kernel<32, 32, true><<<GG, TB, smem_gemm(32, 32)>>>(BA, PB, HB, W_c12, SC + 0, SH + 0, BB);
    conv_sparse_kernel<32, 32, 16, true><<<dim3(SG, 2), TB, smem_sparse(32, 16)>>>(BA, nbr313, PB, HB, W_c12, SC + 0, SH + 0, BB, n, ntiles);
    statsbn_kernel<32><<<148, 512>>>(BB, n, SUM + 64, SQ + 64, g02, b02, SC + 64, SH + 64, CTR + 1);

    gemm_center_kernel<16, 32, false><<<GG, TB, smem_gemm(16, 32)>>>(x, PB, HB, W_c2, nullptr, nullptr, BC);
    conv_sparse_kernel<16, 32, 16, false><<<dim3(SG, 2), TB, smem_sparse(16, 16)>>>(x, nbr313, PB, HB, W_c2, nullptr, nullptr, BC, n, ntiles);

    gemm_center_kernel<32, 32, false><<<GG, TB, smem_gemm(32, 32)>>>(BC, PA, HA, W_c3, nullptr, nullptr, BD);
    conv_sparse_kernel<32, 32, 16, false><<<dim3(SG, 2), TB, smem_sparse(32, 16)>>>(BC, nbr133, PA, HA, W_c3, nullptr, nullptr, BD, n, ntiles);
    statsbn_kernel<32><<<148, 512>>>(BD, n, SUM + 128, SQ + 128, g2, b2, SC + 128, SH + 128, CTR + 2);

    combine_kernel<32><<<(n * 32 + 255) / 256, 256>>>(BD, SC + 128, SH + 128,
                                                      BB, SC + 64,  SH + 64, BC, n * 32);

    // ===== ResBlock (32 -> 64) =====
    gemm_center_kernel<32, 64, false><<<GG, TB, smem_gemm(32, 64)>>>(BC, PB, HB, W_r1, nullptr, nullptr, BA);
    conv_sparse_kernel<32, 64, 16, false><<<dim3(SG, 4), TB, smem_sparse(32, 16)>>>(BC, nbr313, PB, HB, W_r1, nullptr, nullptr, BA, n, ntiles);
    statsbn_kernel<64><<<148, 512>>>(BA, n, SUM + 192, SQ + 192, rg0, rb0, SC + 192, SH + 192, CTR + 3);

    gemm_center_kernel<64, 64, true><<<GG, TB, smem_gemm(64, 64)>>>(BA, PA, HA, W_r12, SC + 192, SH + 192, BB);
    conv_sparse_kernel<64, 64, 16, true><<<dim3(SG, 4), TB, smem_sparse(64, 16)>>>(BA, nbr133, PA, HA, W_r12, SC + 192, SH + 192, BB, n, ntiles);
    statsbn_kernel<64><<<148, 512>>>(BB, n, SUM + 256, SQ + 256, rg02, rb02, SC + 256, SH + 256, CTR + 4);

    gemm_center_kernel<32, 64, false><<<GG, TB, smem_gemm(32, 64)>>>(BC, PA, HA, W_r2, nullptr, nullptr, BD);
    conv_sparse_kernel<32, 64, 16, false><<<dim3(SG, 4), TB, smem_sparse(32, 16)>>>(BC, nbr133, PA, HA, W_r2, nullptr, nullptr, BD, n, ntiles);
    statsbn_kernel<64><<<148, 512>>>(BD, n, SUM + 320, SQ + 320, rg1, rb1, SC + 320, SH + 320, CTR + 5);

    gemm_center_kernel<64, 64, true><<<GG, TB, smem_gemm(64, 64)>>>(BD, PB, HB, W_r3, SC + 320, SH + 320, BE);
    conv_sparse_kernel<64, 64, 16, true><<<dim3(SG, 4), TB, smem_sparse(64, 16)>>>(BD, nbr313, PB, HB, W_r3, SC + 320, SH + 320, BE, n, ntiles);
    statsbn_kernel<64><<<148, 512>>>(BE, n, SUM + 384, SQ + 384, rg2, rb2, SC + 384, SH + 384, CTR + 6);

    combine_kernel<64><<<(n * 64 + 255) / 256, 256>>>(BE, SC + 384, SH + 384,
                                                      BB, SC + 256, SH + 256, out, n * 64);
}

// round 12
// speedup vs baseline: 2.2168x; 1.1917x over previous
#include <cuda_runtime.h>
#include <math.h>

#define NVOX 120000
#define EPSV 1e-5f

// ---------------- scratch (no dynamic alloc allowed) ----------------
__device__ __align__(16) float g_bufA[NVOX * 64];
__device__ __align__(16) float g_bufB[NVOX * 64];
__device__ __align__(16) float g_bufC[NVOX * 64];
__device__ __align__(16) float g_bufD[NVOX * 64];
__device__ __align__(16) float g_bufE[NVOX * 64];
__device__ float g_sum[7 * 64];
__device__ float g_sq [7 * 64];
__device__ float g_sc [7 * 64];
__device__ float g_sh [7 * 64];
__device__ int   g_ctr[8];
__device__ int g_permA[NVOX];
__device__ int g_permB[NVOX];
__device__ int g_maskA[NVOX];
__device__ int g_maskB[NVOX];
__device__ int g_histA[512];
__device__ int g_histB[512];

// ---------------- packed f32x2 helpers ----------------
__device__ __forceinline__ unsigned long long pack2same(float v) {
    unsigned long long r;
    asm("mov.b64 %0, {%1, %1};" : "=l"(r) : "f"(v));
    return r;
}
__device__ __forceinline__ void unpack2(float& lo, float& hi, unsigned long long a) {
    asm("mov.b64 {%0, %1}, %2;" : "=f"(lo), "=f"(hi) : "l"(a));
}
__device__ __forceinline__ void ffma2(unsigned long long& d, unsigned long long a, unsigned long long b) {
    asm("fma.rn.f32x2 %0, %1, %2, %0;" : "+l"(d) : "l"(a), "l"(b));
}

template <int CT>
__device__ __forceinline__ void mac_row(unsigned long long* acc, float v, const float* w) {
    unsigned long long vv = pack2same(v);
    const ulonglong2* w2 = reinterpret_cast<const ulonglong2*>(w);
#pragma unroll
    for (int q = 0; q < CT / 4; q++) {
        ulonglong2 ww = w2[q];
        ffma2(acc[2 * q + 0], vv, ww.x);
        ffma2(acc[2 * q + 1], vv, ww.y);
    }
}

__device__ __forceinline__ float lrelu(float x) { return x > 0.f ? x : 0.01f * x; }

__device__ __forceinline__ float to_tf32(float x) {
    float r;
    asm("cvt.rna.tf32.f32 %0, %1;" : "=f"(r) : "f"(x));
    return r;
}

__device__ __forceinline__ void mma_tf32(float* c, const unsigned* a, unsigned b0, unsigned b1) {
    asm("mma.sync.aligned.m16n8k8.row.col.f32.tf32.tf32.f32 "
        "{%0,%1,%2,%3}, {%4,%5,%6,%7}, {%8,%9}, {%0,%1,%2,%3};"
        : "+f"(c[0]), "+f"(c[1]), "+f"(c[2]), "+f"(c[3])
        : "r"(a[0]), "r"(a[1]), "r"(a[2]), "r"(a[3]), "r"(b0), "r"(b1));
}

// ================= mask-bucket counting sort (both rulebooks) ==============
__global__ void mask_hist_kernel(const int* __restrict__ nbrA, const int* __restrict__ nbrB,
                                 int n, int* __restrict__ histA, int* __restrict__ histB,
                                 int* __restrict__ masksA, int* __restrict__ masksB) {
    const int* nbr = blockIdx.y ? nbrB : nbrA;
    int* hist      = blockIdx.y ? histB : histA;
    int* masks     = blockIdx.y ? masksB : masksA;
    __shared__ int lh[512];
    for (int i = threadIdx.x; i < 512; i += blockDim.x) lh[i] = 0;
    __syncthreads();
    int r = blockIdx.x * blockDim.x + threadIdx.x;
    if (r < n) {
        const int* nb = nbr + (size_t)r * 9;
        int m = 0;
#pragma unroll
        for (int k = 0; k < 9; k++) m |= (nb[k] < n) << k;
        masks[r] = m;
        atomicAdd(&lh[m], 1);
    }
    __syncthreads();
    for (int i = threadIdx.x; i < 512; i += blockDim.x)
        if (lh[i]) atomicAdd(&hist[i], lh[i]);
}

__global__ void scan_kernel(int* __restrict__ histA, int* __restrict__ histB) {
    int* hist = blockIdx.x ? histB : histA;
    __shared__ int tmp[512];
    int t = threadIdx.x;
    tmp[t] = hist[t];
    __syncthreads();
    for (int off = 1; off < 512; off <<= 1) {
        int add = (t >= off) ? tmp[t - off] : 0;
        __syncthreads();
        tmp[t] += add;
        __syncthreads();
    }
    hist[t] = (t == 0) ? 0 : tmp[t - 1];
}

// after scatter, hist[16] = count of center-only rows = dense/sparse boundary.
__global__ void scatter_kernel(const int* __restrict__ masksA, const int* __restrict__ masksB,
                               int n, int* __restrict__ offsA, int* __restrict__ offsB,
                               int* __restrict__ permA, int* __restrict__ permB) {
    const int* masks = blockIdx.y ? masksB : masksA;
    int* offs        = blockIdx.y ? offsB : offsA;
    int* perm        = blockIdx.y ? permB : permA;
    int r = blockIdx.x * blockDim.x + threadIdx.x;
    int lane = threadIdx.x & 31;
    int m = (r < n) ? masks[r] : -1;
    unsigned grp = __match_any_sync(0xffffffffu, m);
    int leader = __ffs(grp) - 1;
    int rank = __popc(grp & ((1u << lane) - 1u));
    int base = 0;
    if (lane == leader && m >= 0) base = atomicAdd(&offs[m], __popc(grp));
    base = __shfl_sync(0xffffffffu, base, leader);
    if (m >= 0) perm[base + rank] = r;
}

// ================= fused conv: dense tf32 GEMM + sparse fp32 gather ========
// Blocks [0, DB): center-only rows perm[0..hist[16]) via m16n8k8 tf32 mma.
// Blocks [DB, DB+SBX*NT): sparse rows perm[hist[16]..n), COUT tiled by 16.
template <int CIN, int COUT, bool AFFINE>
__global__ void __launch_bounds__(256)
fused_conv_kernel(const float* __restrict__ in, const int* __restrict__ nbr,
                  const int* __restrict__ perm, const int* __restrict__ hist,
                  const float* __restrict__ W,
                  const float* __restrict__ sc, const float* __restrict__ sh,
                  float* __restrict__ out, int n, int ntiles, int DB, int SBX) {
    extern __shared__ __align__(16) float sm[];
    const int tid = threadIdx.x;
    const int B16 = __ldg(hist + 16);

    if ((int)blockIdx.x < DB) {
        // ---------------- dense GEMM path ----------------
        constexpr int MX = (CIN > COUT) ? CIN : COUT;
        constexpr int SP = MX + 4;
        constexpr int WP = COUT + 1;
        float* wsm = sm;                    // CIN*WP (tf32)
        float* stg = wsm + CIN * WP;        // 8 warps * 16 * SP
        float* csc = stg + 8 * 16 * SP;     // CIN
        float* csh = csc + CIN;             // CIN
        const int wid = tid >> 5, lane = tid & 31;
        const int gr = lane >> 2, tg = lane & 3;

        if (AFFINE) {
            for (int i = tid; i < CIN; i += 256) { csc[i] = sc[i]; csh[i] = sh[i]; }
        }
        {   // stage center weight slice (k=4), tf32-converted
            const float* Wc = W + 4 * CIN * COUT;
            for (int i = tid; i < CIN * COUT; i += 256) {
                int k = i / COUT, nn = i - k * COUT;
                wsm[k * WP + nn] = to_tf32(Wc[i]);
            }
        }
        __syncthreads();
        float* aw = stg + wid * 16 * SP;

        for (int base = blockIdx.x * 128; base < B16; base += DB * 128) {
            const int wbase = base + wid * 16;
            if (wbase >= B16) continue;
            __syncwarp();
            int prow = -1;
            if (lane < 16 && wbase + lane < B16) prow = perm[wbase + lane];

#pragma unroll
            for (int it = 0; it < CIN / 8; it++) {
                int e = it * 32 + lane;
                int r = e / (CIN / 4), c4 = e - r * (CIN / 4);
                int pr = __shfl_sync(0xffffffffu, prow, r);
                float4 v = make_float4(0.f, 0.f, 0.f, 0.f);
                if (pr >= 0) {
                    v = *reinterpret_cast<const float4*>(in + (size_t)pr * CIN + 4 * c4);
                    if (AFFINE) {
                        v.x = fmaf(v.x, csc[4 * c4 + 0], csh[4 * c4 + 0]);
                        v.y = fmaf(v.y, csc[4 * c4 + 1], csh[4 * c4 + 1]);
                        v.z = fmaf(v.z, csc[4 * c4 + 2], csh[4 * c4 + 2]);
                        v.w = fmaf(v.w, csc[4 * c4 + 3], csh[4 * c4 + 3]);
                    }
                }
                v.x = to_tf32(v.x); v.y = to_tf32(v.y); v.z = to_tf32(v.z); v.w = to_tf32(v.w);
                *reinterpret_cast<float4*>(aw + r * SP + 4 * c4) = v;
            }
            __syncwarp();

            unsigned af[CIN / 8][4];
#pragma unroll
            for (int kt = 0; kt < CIN / 8; kt++) {
                const float* r0 = aw + gr * SP + kt * 8 + tg;
                const float* r1 = aw + (gr + 8) * SP + kt * 8 + tg;
                af[kt][0] = __float_as_uint(r0[0]);
                af[kt][1] = __float_as_uint(r1[0]);
                af[kt][2] = __float_as_uint(r0[4]);
                af[kt][3] = __float_as_uint(r1[4]);
            }

            float cf[COUT / 8][4];
#pragma unroll
            for (int nt = 0; nt < COUT / 8; nt++) {
                cf[nt][0] = cf[nt][1] = cf[nt][2] = cf[nt][3] = 0.f;
#pragma unroll
                for (int kt = 0; kt < CIN / 8; kt++) {
                    unsigned b0 = __float_as_uint(wsm[(kt * 8 + tg) * WP + nt * 8 + gr]);
                    unsigned b1 = __float_as_uint(wsm[(kt * 8 + tg + 4) * WP + nt * 8 + gr]);
                    mma_tf32(cf[nt], af[kt], b0, b1);
                }
            }
            __syncwarp();

#pragma unroll
            for (int nt = 0; nt < COUT / 8; nt++) {
                int col = nt * 8 + 2 * tg;
                aw[gr * SP + col]           = lrelu(cf[nt][0]);
                aw[gr * SP + col + 1]       = lrelu(cf[nt][1]);
                aw[(gr + 8) * SP + col]     = lrelu(cf[nt][2]);
                aw[(gr + 8) * SP + col + 1] = lrelu(cf[nt][3]);
            }
            __syncwarp();

#pragma unroll
            for (int it = 0; it < COUT / 8; it++) {
                int e = it * 32 + lane;
                int r = e / (COUT / 4), c4 = e - r * (COUT / 4);
                int pr = __shfl_sync(0xffffffffu, prow, r);
                if (pr >= 0)
                    *reinterpret_cast<float4*>(out + (size_t)pr * COUT + 4 * c4) =
                        *reinterpret_cast<const float4*>(aw + r * SP + 4 * c4);
            }
        }
    } else {
        // ---------------- sparse gather path (CT = 16) ----------------
        constexpr int CT = 16;
        float* ws  = sm;                    // 9*CIN*CT
        float* csc = ws + 9 * CIN * CT;     // CIN
        float* csh = csc + CIN;             // CIN
        const int s = blockIdx.x - DB;
        const int tbi = s / SBX;            // which COUT tile
        const int sx  = s - tbi * SBX;
        const int tb  = tbi * CT;

        {
            float4* ws4 = reinterpret_cast<float4*>(ws);
            const float4* W4 = reinterpret_cast<const float4*>(W);
            const int tb4 = tb >> 2;
            const int c4w = COUT >> 2;
            constexpr int TOT4 = 9 * CIN * CT / 4;
            constexpr int Q4 = CT / 4;
#pragma unroll 4
            for (int i = tid; i < TOT4; i += 256) {
                int r = i / Q4;
                int q = i - r * Q4;
                ws4[i] = W4[r * c4w + tb4 + q];
            }
        }
        if (AFFINE) {
            for (int i = tid; i < CIN; i += 256) { csc[i] = sc[i]; csh[i] = sh[i]; }
        }
        __syncthreads();

        const int t0 = B16 >> 8;
        for (int t = t0 + sx; t < ntiles; t += SBX) {
            const int gid = t * 256 + tid;
            const bool rok = (gid < n) && (gid >= B16);
            const int row = rok ? perm[gid] : 0;

            const int* nb = nbr + (size_t)row * 9;
            int idx[9];
#pragma unroll
            for (int k = 0; k < 9; k++) idx[k] = rok ? __ldg(nb + k) : n;

            unsigned long long acc[CT / 2];
#pragma unroll
            for (int i = 0; i < CT / 2; i++) acc[i] = 0ull;

#pragma unroll
            for (int k = 0; k < 9; k++) {
                const int j = idx[k];
                const bool v = j < n;
                if (!__any_sync(0xffffffffu, v)) continue;
                const float4* xr = reinterpret_cast<const float4*>(in + (size_t)j * CIN);
                const float* wk = ws + k * CIN * CT;
#pragma unroll
                for (int c4 = 0; c4 < CIN / 4; c4++) {
                    float4 val = make_float4(0.f, 0.f, 0.f, 0.f);
                    if (v) {
                        val = xr[c4];
                        if (AFFINE) {
                            val.x = fmaf(val.x, csc[4 * c4 + 0], csh[4 * c4 + 0]);
                            val.y = fmaf(val.y, csc[4 * c4 + 1], csh[4 * c4 + 1]);
                            val.z = fmaf(val.z, csc[4 * c4 + 2], csh[4 * c4 + 2]);
                            val.w = fmaf(val.w, csc[4 * c4 + 3], csh[4 * c4 + 3]);
                        }
                    }
                    const float* w0 = wk + (4 * c4) * CT;
                    mac_row<CT>(acc, val.x, w0);
                    mac_row<CT>(acc, val.y, w0 + CT);
                    mac_row<CT>(acc, val.z, w0 + 2 * CT);
                    mac_row<CT>(acc, val.w, w0 + 3 * CT);
                }
            }

            if (rok) {
                float* o = out + (size_t)row * COUT + tb;
#pragma unroll
                for (int i = 0; i < CT / 2; i++) {
                    float lo, hi;
                    unpack2(lo, hi, acc[i]);
                    reinterpret_cast<float2*>(o)[i] = make_float2(lrelu(lo), lrelu(hi));
                }
            }
        }
    }
}

// ---------------- per-channel sum/sumsq + last-block BN finalize ------------
template <int C>
__global__ void statsbn_kernel(const float* __restrict__ d, int n,
                               float* __restrict__ sum, float* __restrict__ sq,
                               const float* __restrict__ g, const float* __restrict__ b,
                               float* __restrict__ scale, float* __restrict__ shift,
                               int* __restrict__ ctr) {
    __shared__ float ss[512];
    __shared__ float qq[512];
    __shared__ int last;
    const int tid = threadIdx.x;
    const int col = tid % C;
    const int rl  = tid / C;
    const int rpb = blockDim.x / C;
    float s = 0.f, q = 0.f;
    for (int r = blockIdx.x * rpb + rl; r < n; r += gridDim.x * rpb) {
        float v = d[(size_t)r * C + col];
        s += v; q += v * v;
    }
    ss[tid] = s; qq[tid] = q;
    __syncthreads();
    for (int off = blockDim.x / 2; off >= C; off >>= 1) {
        if (tid < off) { ss[tid] += ss[tid + off]; qq[tid] += qq[tid + off]; }
        __syncthreads();
    }
    if (tid < C) {
        atomicAdd(sum + tid, ss[tid]);
        atomicAdd(sq + tid, qq[tid]);
    }
    __threadfence();
    __syncthreads();
    if (tid == 0) last = (atomicAdd(ctr, 1) == (int)gridDim.x - 1);
    __syncthreads();
    if (last && tid < C) {
        float inv_n = 1.0f / (float)n;
        float m   = __ldcg(sum + tid) * inv_n;
        float var = __ldcg(sq + tid) * inv_n - m * m;   // biased variance
        float sc2 = g[tid] / sqrtf(var + EPSV);
        scale[tid] = sc2;
        shift[tid] = b[tid] - m * sc2;
    }
}

// ---------------- out = aff(a) + aff(b) ----------------
template <int C>
__global__ void combine_kernel(const float* __restrict__ a, const float* __restrict__ sa, const float* __restrict__ ha,
                               const float* __restrict__ b, const float* __restrict__ sb, const float* __restrict__ hb,
                               float* __restrict__ o, int total) {
    int i = blockIdx.x * blockDim.x + threadIdx.x;
    if (i >= total) return;
    int c = i & (C - 1);
    o[i] = fmaf(a[i], sa[c], ha[c]) + fmaf(b[i], sb[c], hb[c]);
}

__global__ void zero_kernel(float* __restrict__ sum, float* __restrict__ sq,
                            int* __restrict__ hA, int* __restrict__ hB,
                            int* __restrict__ ctr) {
    int i = blockIdx.x * blockDim.x + threadIdx.x;
    if (i < 7 * 64) { sum[i] = 0.f; sq[i] = 0.f; }
    if (i < 512) { hA[i] = 0; hB[i] = 0; }
    if (i < 8) ctr[i] = 0;
}

// ---------------- host ----------------
static constexpr size_t smem_fused(int cin, int cout) {
    int mx = cin > cout ? cin : cout;
    size_t gemm = (size_t)(cin * (cout + 1) + 8 * 16 * (mx + 4) + 2 * cin) * sizeof(float);
    size_t sparse = (size_t)(9 * cin * 16 + 2 * cin) * sizeof(float);
    return gemm > sparse ? gemm : sparse;
}

extern "C" void kernel_launch(void* const* d_in, const int* in_sizes, int n_in,
                              void* d_out, int out_size) {
    const float* x      = (const float*)d_in[0];
    const int*   nbr133 = (const int*)  d_in[1];
    const int*   nbr313 = (const int*)  d_in[2];
    const float* W_c1   = (const float*)d_in[3];
    const float* g0     = (const float*)d_in[4];
    const float* b0     = (const float*)d_in[5];
    const float* W_c12  = (const float*)d_in[6];
    const float* g02    = (const float*)d_in[7];
    const float* b02    = (const float*)d_in[8];
    const float* W_c2   = (const float*)d_in[9];
    const float* W_c3   = (const float*)d_in[10];
    const float* g2     = (const float*)d_in[11];
    const float* b2     = (const float*)d_in[12];
    const float* W_r1   = (const float*)d_in[13];
    const float* rg0    = (const float*)d_in[14];
    const float* rb0    = (const float*)d_in[15];
    const float* W_r12  = (const float*)d_in[16];
    const float* rg02   = (const float*)d_in[17];
    const float* rb02   = (const float*)d_in[18];
    const float* W_r2   = (const float*)d_in[19];
    const float* rg1    = (const float*)d_in[20];
    const float* rb1    = (const float*)d_in[21];
    const float* W_r3   = (const float*)d_in[22];
    const float* rg2    = (const float*)d_in[23];
    const float* rb2    = (const float*)d_in[24];
    float* out = (float*)d_out;

    const int n = in_sizes[0] / 16;   // 120000

    float *BA, *BB, *BC, *BD, *BE, *SUM, *SQ, *SC, *SH;
    int *PA, *PB, *MA, *MB, *HA, *HB, *CTR;
    cudaGetSymbolAddress((void**)&BA,  g_bufA);
    cudaGetSymbolAddress((void**)&BB,  g_bufB);
    cudaGetSymbolAddress((void**)&BC,  g_bufC);
    cudaGetSymbolAddress((void**)&BD,  g_bufD);
    cudaGetSymbolAddress((void**)&BE,  g_bufE);
    cudaGetSymbolAddress((void**)&SUM, g_sum);
    cudaGetSymbolAddress((void**)&SQ,  g_sq);
    cudaGetSymbolAddress((void**)&SC,  g_sc);
    cudaGetSymbolAddress((void**)&SH,  g_sh);
    cudaGetSymbolAddress((void**)&PA,  g_permA);
    cudaGetSymbolAddress((void**)&PB,  g_permB);
    cudaGetSymbolAddress((void**)&MA,  g_maskA);
    cudaGetSymbolAddress((void**)&MB,  g_maskB);
    cudaGetSymbolAddress((void**)&HA,  g_histA);
    cudaGetSymbolAddress((void**)&HB,  g_histB);
    cudaGetSymbolAddress((void**)&CTR, g_ctr);

    static int inited = 0;
    if (!inited) {
        inited = 1;
        cudaFuncSetAttribute((const void*)fused_conv_kernel<64, 64, true>,
                             cudaFuncAttributeMaxDynamicSharedMemorySize, (int)smem_fused(64, 64));
        cudaFuncSetAttribute((const void*)fused_conv_kernel<32, 64, false>,
                             cudaFuncAttributeMaxDynamicSharedMemorySize, (int)smem_fused(32, 64));
    }

    const int TB = 256;
    const int ntiles = (n + TB - 1) / TB;
    const int G = ntiles;
    const int DB  = 296;   // dense gemm blocks (persistent, ~2/SM)
    const int SBX = 96;    // sparse blocks per COUT tile (~75 active tiles)

    // ----- prologue -----
    zero_kernel<<<2, 512>>>(SUM, SQ, HA, HB, CTR);
    mask_hist_kernel<<<dim3(G, 2), TB>>>(nbr133, nbr313, n, HA, HB, MA, MB);
    scan_kernel<<<2, 512>>>(HA, HB);
    scatter_kernel<<<dim3(G, 2), TB>>>(MA, MB, n, HA, HB, PA, PB);

    // ===== ResContextBlock (16 -> 32) =====
    fused_conv_kernel<16, 32, false><<<DB + SBX * 2, TB, smem_fused(16, 32)>>>(
        x, nbr133, PA, HA, W_c1, nullptr, nullptr, BA, n, ntiles, DB, SBX);
    statsbn_kernel<32><<<148, 512>>>(BA, n, SUM + 0, SQ + 0, g0, b0, SC + 0, SH + 0, CTR + 0);

    fused_conv_kernel<32, 32, true><<<DB + SBX * 2, TB, smem_fused(32, 32)>>>(
        BA, nbr313, PB, HB, W_c12, SC + 0, SH + 0, BB, n, ntiles, DB, SBX);
    statsbn_kernel<32><<<148, 512>>>(BB, n, SUM + 64, SQ + 64, g02, b02, SC + 64, SH + 64, CTR + 1);

    fused_conv_kernel<16, 32, false><<<DB + SBX * 2, TB, smem_fused(16, 32)>>>(
        x, nbr313, PB, HB, W_c2, nullptr, nullptr, BC, n, ntiles, DB, SBX);

    fused_conv_kernel<32, 32, false><<<DB + SBX * 2, TB, smem_fused(32, 32)>>>(
        BC, nbr133, PA, HA, W_c3, nullptr, nullptr, BD, n, ntiles, DB, SBX);
    statsbn_kernel<32><<<148, 512>>>(BD, n, SUM + 128, SQ + 128, g2, b2, SC + 128, SH + 128, CTR + 2);

    combine_kernel<32><<<(n * 32 + 255) / 256, 256>>>(BD, SC + 128, SH + 128,
                                                      BB, SC + 64,  SH + 64, BC, n * 32);

    // ===== ResBlock (32 -> 64) =====
    fused_conv_kernel<32, 64, false><<<DB + SBX * 4, TB, smem_fused(32, 64)>>>(
        BC, nbr313, PB, HB, W_r1, nullptr, nullptr, BA, n, ntiles, DB, SBX);
    statsbn_kernel<64><<<148, 512>>>(BA, n, SUM + 192, SQ + 192, rg0, rb0, SC + 192, SH + 192, CTR + 3);

    fused_conv_kernel<64, 64, true><<<DB + SBX * 4, TB, smem_fused(64, 64)>>>(
        BA, nbr133, PA, HA, W_r12, SC + 192, SH + 192, BB, n, ntiles, DB, SBX);
    statsbn_kernel<64><<<148, 512>>>(BB, n, SUM + 256, SQ + 256, rg02, rb02, SC + 256, SH + 256, CTR + 4);

    fused_conv_kernel<32, 64, false><<<DB + SBX * 4, TB, smem_fused(32, 64)>>>(
        BC, nbr133, PA, HA, W_r2, nullptr, nullptr, BD, n, ntiles, DB, SBX);
    statsbn_kernel<64><<<148, 512>>>(BD, n, SUM + 320, SQ + 320, rg1, rb1, SC + 320, SH + 320, CTR + 5);

    fused_conv_kernel<64, 64, true><<<DB + SBX * 4, TB, smem_fused(64, 64)>>>(
        BD, nbr313, PB, HB, W_r3, SC + 320, SH + 320, BE, n, ntiles, DB, SBX);
    statsbn_kernel<64><<<148, 512>>>(BE, n, SUM + 384, SQ + 384, rg2, rb2, SC + 384, SH + 384, CTR + 6);

    combine_kernel<64><<<(n * 64 + 255) / 256, 256>>>(BE, SC + 384, SH + 384,
                                                      BB, SC + 256, SH + 256, out, n * 64);
}

// round 13
// speedup vs baseline: 2.6328x; 1.1876x over previous
#include <cuda_runtime.h>
#include <math.h>

#define NVOX 120000
#define EPSV 1e-5f

// ---------------- scratch (no dynamic alloc allowed) ----------------
__device__ __align__(16) float g_bufA[NVOX * 64];
__device__ __align__(16) float g_bufB[NVOX * 64];
__device__ __align__(16) float g_bufC[NVOX * 64];
__device__ __align__(16) float g_bufD[NVOX * 64];
__device__ __align__(16) float g_bufE[NVOX * 64];
__device__ float g_sum[7 * 64];
__device__ float g_sq [7 * 64];
__device__ float g_sc [7 * 64];
__device__ float g_sh [7 * 64];
__device__ int   g_ctr[8];
__device__ int g_permA[NVOX];
__device__ int g_permB[NVOX];
__device__ int g_maskA[NVOX];
__device__ int g_maskB[NVOX];
__device__ int g_histA[512];
__device__ int g_histB[512];

// ---------------- packed f32x2 helpers ----------------
__device__ __forceinline__ unsigned long long pack2same(float v) {
    unsigned long long r;
    asm("mov.b64 %0, {%1, %1};" : "=l"(r) : "f"(v));
    return r;
}
__device__ __forceinline__ void unpack2(float& lo, float& hi, unsigned long long a) {
    asm("mov.b64 {%0, %1}, %2;" : "=f"(lo), "=f"(hi) : "l"(a));
}
__device__ __forceinline__ void ffma2(unsigned long long& d, unsigned long long a, unsigned long long b) {
    asm("fma.rn.f32x2 %0, %1, %2, %0;" : "+l"(d) : "l"(a), "l"(b));
}

template <int CT>
__device__ __forceinline__ void mac_row(unsigned long long* acc, float v, const float* w) {
    unsigned long long vv = pack2same(v);
    const ulonglong2* w2 = reinterpret_cast<const ulonglong2*>(w);
#pragma unroll
    for (int q = 0; q < CT / 4; q++) {
        ulonglong2 ww = w2[q];
        ffma2(acc[2 * q + 0], vv, ww.x);
        ffma2(acc[2 * q + 1], vv, ww.y);
    }
}

__device__ __forceinline__ float lrelu(float x) { return x > 0.f ? x : 0.01f * x; }

__device__ __forceinline__ float to_tf32(float x) {
    float r;
    asm("cvt.rna.tf32.f32 %0, %1;" : "=f"(r) : "f"(x));
    return r;
}

__device__ __forceinline__ void mma_tf32(float* c, const unsigned* a, unsigned b0, unsigned b1) {
    asm("mma.sync.aligned.m16n8k8.row.col.f32.tf32.tf32.f32 "
        "{%0,%1,%2,%3}, {%4,%5,%6,%7}, {%8,%9}, {%0,%1,%2,%3};"
        : "+f"(c[0]), "+f"(c[1]), "+f"(c[2]), "+f"(c[3])
        : "r"(a[0]), "r"(a[1]), "r"(a[2]), "r"(a[3]), "r"(b0), "r"(b1));
}

// ================= mask-bucket counting sort (both rulebooks) ==============
__global__ void mask_hist_kernel(const int* __restrict__ nbrA, const int* __restrict__ nbrB,
                                 int n, int* __restrict__ histA, int* __restrict__ histB,
                                 int* __restrict__ masksA, int* __restrict__ masksB) {
    const int* nbr = blockIdx.y ? nbrB : nbrA;
    int* hist      = blockIdx.y ? histB : histA;
    int* masks     = blockIdx.y ? masksB : masksA;
    __shared__ int lh[512];
    for (int i = threadIdx.x; i < 512; i += blockDim.x) lh[i] = 0;
    __syncthreads();
    int r = blockIdx.x * blockDim.x + threadIdx.x;
    if (r < n) {
        const int* nb = nbr + (size_t)r * 9;
        int m = 0;
#pragma unroll
        for (int k = 0; k < 9; k++) m |= (nb[k] < n) << k;
        masks[r] = m;
        atomicAdd(&lh[m], 1);
    }
    __syncthreads();
    for (int i = threadIdx.x; i < 512; i += blockDim.x)
        if (lh[i]) atomicAdd(&hist[i], lh[i]);
}

__global__ void scan_kernel(int* __restrict__ histA, int* __restrict__ histB) {
    int* hist = blockIdx.x ? histB : histA;
    __shared__ int tmp[512];
    int t = threadIdx.x;
    tmp[t] = hist[t];
    __syncthreads();
    for (int off = 1; off < 512; off <<= 1) {
        int add = (t >= off) ? tmp[t - off] : 0;
        __syncthreads();
        tmp[t] += add;
        __syncthreads();
    }
    hist[t] = (t == 0) ? 0 : tmp[t - 1];
}

__global__ void scatter_kernel(const int* __restrict__ masksA, const int* __restrict__ masksB,
                               int n, int* __restrict__ offsA, int* __restrict__ offsB,
                               int* __restrict__ permA, int* __restrict__ permB) {
    const int* masks = blockIdx.y ? masksB : masksA;
    int* offs        = blockIdx.y ? offsB : offsA;
    int* perm        = blockIdx.y ? permB : permA;
    int r = blockIdx.x * blockDim.x + threadIdx.x;
    int lane = threadIdx.x & 31;
    int m = (r < n) ? masks[r] : -1;
    unsigned grp = __match_any_sync(0xffffffffu, m);
    int leader = __ffs(grp) - 1;
    int rank = __popc(grp & ((1u << lane) - 1u));
    int base = 0;
    if (lane == leader && m >= 0) base = atomicAdd(&offs[m], __popc(grp));
    base = __shfl_sync(0xffffffffu, base, leader);
    if (m >= 0) perm[base + rank] = r;
}

// ================= fused conv body: dense tf32 GEMM + sparse fp32 gather ===
template <int CIN, int COUT, bool AFFINE>
__device__ __forceinline__ void
fused_conv_body(float* sm,
                const float* __restrict__ in, const int* __restrict__ nbr,
                const int* __restrict__ perm, const int* __restrict__ hist,
                const float* __restrict__ W,
                const float* __restrict__ sc, const float* __restrict__ sh,
                float* __restrict__ out, int n, int ntiles, int DB, int SBX) {
    const int tid = threadIdx.x;
    const int B16 = __ldg(hist + 16);

    if ((int)blockIdx.x < DB) {
        // ---------------- dense GEMM path ----------------
        constexpr int MX = (CIN > COUT) ? CIN : COUT;
        constexpr int SP = MX + 4;
        constexpr int WP = COUT + 1;
        float* wsm = sm;                    // CIN*WP (tf32)
        float* stg = wsm + CIN * WP;        // 8 warps * 16 * SP
        float* csc = stg + 8 * 16 * SP;     // CIN
        float* csh = csc + CIN;             // CIN
        const int wid = tid >> 5, lane = tid & 31;
        const int gr = lane >> 2, tg = lane & 3;

        if (AFFINE) {
            for (int i = tid; i < CIN; i += 256) { csc[i] = sc[i]; csh[i] = sh[i]; }
        }
        {   // stage center weight slice (k=4), tf32-converted
            const float* Wc = W + 4 * CIN * COUT;
            for (int i = tid; i < CIN * COUT; i += 256) {
                int k = i / COUT, nn = i - k * COUT;
                wsm[k * WP + nn] = to_tf32(Wc[i]);
            }
        }
        __syncthreads();
        float* aw = stg + wid * 16 * SP;

        for (int base = blockIdx.x * 128; base < B16; base += DB * 128) {
            const int wbase = base + wid * 16;
            if (wbase >= B16) continue;
            __syncwarp();
            int prow = -1;
            if (lane < 16 && wbase + lane < B16) prow = perm[wbase + lane];

#pragma unroll
            for (int it = 0; it < CIN / 8; it++) {
                int e = it * 32 + lane;
                int r = e / (CIN / 4), c4 = e - r * (CIN / 4);
                int pr = __shfl_sync(0xffffffffu, prow, r);
                float4 v = make_float4(0.f, 0.f, 0.f, 0.f);
                if (pr >= 0) {
                    v = *reinterpret_cast<const float4*>(in + (size_t)pr * CIN + 4 * c4);
                    if (AFFINE) {
                        v.x = fmaf(v.x, csc[4 * c4 + 0], csh[4 * c4 + 0]);
                        v.y = fmaf(v.y, csc[4 * c4 + 1], csh[4 * c4 + 1]);
                        v.z = fmaf(v.z, csc[4 * c4 + 2], csh[4 * c4 + 2]);
                        v.w = fmaf(v.w, csc[4 * c4 + 3], csh[4 * c4 + 3]);
                    }
                }
                v.x = to_tf32(v.x); v.y = to_tf32(v.y); v.z = to_tf32(v.z); v.w = to_tf32(v.w);
                *reinterpret_cast<float4*>(aw + r * SP + 4 * c4) = v;
            }
            __syncwarp();

            unsigned af[CIN / 8][4];
#pragma unroll
            for (int kt = 0; kt < CIN / 8; kt++) {
                const float* r0 = aw + gr * SP + kt * 8 + tg;
                const float* r1 = aw + (gr + 8) * SP + kt * 8 + tg;
                af[kt][0] = __float_as_uint(r0[0]);
                af[kt][1] = __float_as_uint(r1[0]);
                af[kt][2] = __float_as_uint(r0[4]);
                af[kt][3] = __float_as_uint(r1[4]);
            }

            float cf[COUT / 8][4];
#pragma unroll
            for (int nt = 0; nt < COUT / 8; nt++) {
                cf[nt][0] = cf[nt][1] = cf[nt][2] = cf[nt][3] = 0.f;
#pragma unroll
                for (int kt = 0; kt < CIN / 8; kt++) {
                    unsigned b0 = __float_as_uint(wsm[(kt * 8 + tg) * WP + nt * 8 + gr]);
                    unsigned b1 = __float_as_uint(wsm[(kt * 8 + tg + 4) * WP + nt * 8 + gr]);
                    mma_tf32(cf[nt], af[kt], b0, b1);
                }
            }
            __syncwarp();

#pragma unroll
            for (int nt = 0; nt < COUT / 8; nt++) {
                int col = nt * 8 + 2 * tg;
                aw[gr * SP + col]           = lrelu(cf[nt][0]);
                aw[gr * SP + col + 1]       = lrelu(cf[nt][1]);
                aw[(gr + 8) * SP + col]     = lrelu(cf[nt][2]);
                aw[(gr + 8) * SP + col + 1] = lrelu(cf[nt][3]);
            }
            __syncwarp();

#pragma unroll
            for (int it = 0; it < COUT / 8; it++) {
                int e = it * 32 + lane;
                int r = e / (COUT / 4), c4 = e - r * (COUT / 4);
                int pr = __shfl_sync(0xffffffffu, prow, r);
                if (pr >= 0)
                    *reinterpret_cast<float4*>(out + (size_t)pr * COUT + 4 * c4) =
                        *reinterpret_cast<const float4*>(aw + r * SP + 4 * c4);
            }
        }
    } else {
        // ---------------- sparse gather path (CT = 16) ----------------
        constexpr int CT = 16;
        float* ws  = sm;                    // 9*CIN*CT
        float* csc = ws + 9 * CIN * CT;     // CIN
        float* csh = csc + CIN;             // CIN
        const int s = blockIdx.x - DB;
        const int tbi = s / SBX;            // which COUT tile
        const int sx  = s - tbi * SBX;
        const int tb  = tbi * CT;

        {
            float4* ws4 = reinterpret_cast<float4*>(ws);
            const float4* W4 = reinterpret_cast<const float4*>(W);
            const int tb4 = tb >> 2;
            const int c4w = COUT >> 2;
            constexpr int TOT4 = 9 * CIN * CT / 4;
            constexpr int Q4 = CT / 4;
#pragma unroll 4
            for (int i = tid; i < TOT4; i += 256) {
                int r = i / Q4;
                int q = i - r * Q4;
                ws4[i] = W4[r * c4w + tb4 + q];
            }
        }
        if (AFFINE) {
            for (int i = tid; i < CIN; i += 256) { csc[i] = sc[i]; csh[i] = sh[i]; }
        }
        __syncthreads();

        const int t0 = B16 >> 8;
        for (int t = t0 + sx; t < ntiles; t += SBX) {
            const int gid = t * 256 + tid;
            const bool rok = (gid < n) && (gid >= B16);
            const int row = rok ? perm[gid] : 0;

            const int* nb = nbr + (size_t)row * 9;
            int idx[9];
#pragma unroll
            for (int k = 0; k < 9; k++) idx[k] = rok ? __ldg(nb + k) : n;

            unsigned long long acc[CT / 2];
#pragma unroll
            for (int i = 0; i < CT / 2; i++) acc[i] = 0ull;

#pragma unroll
            for (int k = 0; k < 9; k++) {
                const int j = idx[k];
                const bool v = j < n;
                if (!__any_sync(0xffffffffu, v)) continue;
                const float4* xr = reinterpret_cast<const float4*>(in + (size_t)j * CIN);
                const float* wk = ws + k * CIN * CT;
#pragma unroll
                for (int c4 = 0; c4 < CIN / 4; c4++) {
                    float4 val = make_float4(0.f, 0.f, 0.f, 0.f);
                    if (v) {
                        val = xr[c4];
                        if (AFFINE) {
                            val.x = fmaf(val.x, csc[4 * c4 + 0], csh[4 * c4 + 0]);
                            val.y = fmaf(val.y, csc[4 * c4 + 1], csh[4 * c4 + 1]);
                            val.z = fmaf(val.z, csc[4 * c4 + 2], csh[4 * c4 + 2]);
                            val.w = fmaf(val.w, csc[4 * c4 + 3], csh[4 * c4 + 3]);
                        }
                    }
                    const float* w0 = wk + (4 * c4) * CT;
                    mac_row<CT>(acc, val.x, w0);
                    mac_row<CT>(acc, val.y, w0 + CT);
                    mac_row<CT>(acc, val.z, w0 + 2 * CT);
                    mac_row<CT>(acc, val.w, w0 + 3 * CT);
                }
            }

            if (rok) {
                float* o = out + (size_t)row * COUT + tb;
#pragma unroll
                for (int i = 0; i < CT / 2; i++) {
                    float lo, hi;
                    unpack2(lo, hi, acc[i]);
                    reinterpret_cast<float2*>(o)[i] = make_float2(lrelu(lo), lrelu(hi));
                }
            }
        }
    }
}

// dual-problem wrapper: blockIdx.y selects the conv problem
template <int CIN, int COUT, bool AFF1, bool AFF2>
__global__ void __launch_bounds__(256)
fused_conv_dual(const float* __restrict__ in1, const int* __restrict__ nbr1,
                const int* __restrict__ perm1, const int* __restrict__ hist1,
                const float* __restrict__ W1, const float* __restrict__ sc1,
                const float* __restrict__ sh1, float* __restrict__ out1,
                const float* __restrict__ in2, const int* __restrict__ nbr2,
                const int* __restrict__ perm2, const int* __restrict__ hist2,
                const float* __restrict__ W2, const float* __restrict__ sc2,
                const float* __restrict__ sh2, float* __restrict__ out2,
                int n, int ntiles, int DB, int SBX) {
    extern __shared__ __align__(16) float sm[];
    if (blockIdx.y == 0)
        fused_conv_body<CIN, COUT, AFF1>(sm, in1, nbr1, perm1, hist1, W1, sc1, sh1, out1, n, ntiles, DB, SBX);
    else
        fused_conv_body<CIN, COUT, AFF2>(sm, in2, nbr2, perm2, hist2, W2, sc2, sh2, out2, n, ntiles, DB, SBX);
}

// ---------------- per-channel sum/sumsq + last-block BN finalize (dual) -----
template <int C>
__device__ __forceinline__ void
statsbn_body(const float* __restrict__ d, int n,
             float* __restrict__ sum, float* __restrict__ sq,
             const float* __restrict__ g, const float* __restrict__ b,
             float* __restrict__ scale, float* __restrict__ shift,
             int* __restrict__ ctr) {
    __shared__ float ss[512];
    __shared__ float qq[512];
    __shared__ int last;
    const int tid = threadIdx.x;
    const int col = tid % C;
    const int rl  = tid / C;
    const int rpb = 512 / C;
    float s = 0.f, q = 0.f;
    for (int r = blockIdx.x * rpb + rl; r < n; r += gridDim.x * rpb) {
        float v = d[(size_t)r * C + col];
        s += v; q += v * v;
    }
    ss[tid] = s; qq[tid] = q;
    __syncthreads();
    for (int off = 256; off >= C; off >>= 1) {
        if (tid < off) { ss[tid] += ss[tid + off]; qq[tid] += qq[tid + off]; }
        __syncthreads();
    }
    if (tid < C) {
        atomicAdd(sum + tid, ss[tid]);
        atomicAdd(sq + tid, qq[tid]);
    }
    __threadfence();
    __syncthreads();
    if (tid == 0) last = (atomicAdd(ctr, 1) == (int)gridDim.x - 1);
    __syncthreads();
    if (last && tid < C) {
        float inv_n = 1.0f / (float)n;
        float m   = __ldcg(sum + tid) * inv_n;
        float var = __ldcg(sq + tid) * inv_n - m * m;   // biased variance
        float sc2 = g[tid] / sqrtf(var + EPSV);
        scale[tid] = sc2;
        shift[tid] = b[tid] - m * sc2;
    }
}

template <int C>
__global__ void statsbn_dual(const float* __restrict__ d1, float* __restrict__ sum1, float* __restrict__ sq1,
                             const float* __restrict__ g1, const float* __restrict__ b1,
                             float* __restrict__ scale1, float* __restrict__ shift1, int* __restrict__ ctr1,
                             const float* __restrict__ d2, float* __restrict__ sum2, float* __restrict__ sq2,
                             const float* __restrict__ g2, const float* __restrict__ b2,
                             float* __restrict__ scale2, float* __restrict__ shift2, int* __restrict__ ctr2,
                             int n) {
    if (blockIdx.y == 0) statsbn_body<C>(d1, n, sum1, sq1, g1, b1, scale1, shift1, ctr1);
    else                 statsbn_body<C>(d2, n, sum2, sq2, g2, b2, scale2, shift2, ctr2);
}

template <int C>
__global__ void statsbn_kernel(const float* __restrict__ d, int n,
                               float* __restrict__ sum, float* __restrict__ sq,
                               const float* __restrict__ g, const float* __restrict__ b,
                               float* __restrict__ scale, float* __restrict__ shift,
                               int* __restrict__ ctr) {
    statsbn_body<C>(d, n, sum, sq, g, b, scale, shift, ctr);
}

// ---------------- out = aff(a) + aff(b) ----------------
template <int C>
__global__ void combine_kernel(const float* __restrict__ a, const float* __restrict__ sa, const float* __restrict__ ha,
                               const float* __restrict__ b, const float* __restrict__ sb, const float* __restrict__ hb,
                               float* __restrict__ o, int total) {
    int i = blockIdx.x * blockDim.x + threadIdx.x;
    if (i >= total) return;
    int c = i & (C - 1);
    o[i] = fmaf(a[i], sa[c], ha[c]) + fmaf(b[i], sb[c], hb[c]);
}

__global__ void zero_kernel(float* __restrict__ sum, float* __restrict__ sq,
                            int* __restrict__ hA, int* __restrict__ hB,
                            int* __restrict__ ctr) {
    int i = blockIdx.x * blockDim.x + threadIdx.x;
    if (i < 7 * 64) { sum[i] = 0.f; sq[i] = 0.f; }
    if (i < 512) { hA[i] = 0; hB[i] = 0; }
    if (i < 8) ctr[i] = 0;
}

// ---------------- host ----------------
static constexpr size_t smem_fused(int cin, int cout) {
    int mx = cin > cout ? cin : cout;
    size_t gemm = (size_t)(cin * (cout + 1) + 8 * 16 * (mx + 4) + 2 * cin) * sizeof(float);
    size_t sparse = (size_t)(9 * cin * 16 + 2 * cin) * sizeof(float);
    return gemm > sparse ? gemm : sparse;
}

extern "C" void kernel_launch(void* const* d_in, const int* in_sizes, int n_in,
                              void* d_out, int out_size) {
    const float* x      = (const float*)d_in[0];
    const int*   nbr133 = (const int*)  d_in[1];
    const int*   nbr313 = (const int*)  d_in[2];
    const float* W_c1   = (const float*)d_in[3];
    const float* g0     = (const float*)d_in[4];
    const float* b0     = (const float*)d_in[5];
    const float* W_c12  = (const float*)d_in[6];
    const float* g02    = (const float*)d_in[7];
    const float* b02    = (const float*)d_in[8];
    const float* W_c2   = (const float*)d_in[9];
    const float* W_c3   = (const float*)d_in[10];
    const float* g2     = (const float*)d_in[11];
    const float* b2     = (const float*)d_in[12];
    const float* W_r1   = (const float*)d_in[13];
    const float* rg0    = (const float*)d_in[14];
    const float* rb0    = (const float*)d_in[15];
    const float* W_r12  = (const float*)d_in[16];
    const float* rg02   = (const float*)d_in[17];
    const float* rb02   = (const float*)d_in[18];
    const float* W_r2   = (const float*)d_in[19];
    const float* rg1    = (const float*)d_in[20];
    const float* rb1    = (const float*)d_in[21];
    const float* W_r3   = (const float*)d_in[22];
    const float* rg2    = (const float*)d_in[23];
    const float* rb2    = (const float*)d_in[24];
    float* out = (float*)d_out;

    const int n = in_sizes[0] / 16;   // 120000

    float *BA, *BB, *BC, *BD, *BE, *SUM, *SQ, *SC, *SH;
    int *PA, *PB, *MA, *MB, *HA, *HB, *CTR;
    cudaGetSymbolAddress((void**)&BA,  g_bufA);
    cudaGetSymbolAddress((void**)&BB,  g_bufB);
    cudaGetSymbolAddress((void**)&BC,  g_bufC);
    cudaGetSymbolAddress((void**)&BD,  g_bufD);
    cudaGetSymbolAddress((void**)&BE,  g_bufE);
    cudaGetSymbolAddress((void**)&SUM, g_sum);
    cudaGetSymbolAddress((void**)&SQ,  g_sq);
    cudaGetSymbolAddress((void**)&SC,  g_sc);
    cudaGetSymbolAddress((void**)&SH,  g_sh);
    cudaGetSymbolAddress((void**)&PA,  g_permA);
    cudaGetSymbolAddress((void**)&PB,  g_permB);
    cudaGetSymbolAddress((void**)&MA,  g_maskA);
    cudaGetSymbolAddress((void**)&MB,  g_maskB);
    cudaGetSymbolAddress((void**)&HA,  g_histA);
    cudaGetSymbolAddress((void**)&HB,  g_histB);
    cudaGetSymbolAddress((void**)&CTR, g_ctr);

    static int inited = 0;
    if (!inited) {
        inited = 1;
        cudaFuncSetAttribute((const void*)fused_conv_dual<64, 64, true, true>,
                             cudaFuncAttributeMaxDynamicSharedMemorySize, (int)smem_fused(64, 64));
        cudaFuncSetAttribute((const void*)fused_conv_dual<32, 64, false, false>,
                             cudaFuncAttributeMaxDynamicSharedMemorySize, (int)smem_fused(32, 64));
    }

    const int TB = 256;
    const int ntiles = (n + TB - 1) / TB;
    const int G = ntiles;
    const int DB  = 148;   // dense gemm blocks per problem slice
    const int SBX = 64;    // sparse blocks per COUT tile per slice

    // ----- prologue (4 nodes) -----
    zero_kernel<<<2, 512>>>(SUM, SQ, HA, HB, CTR);
    mask_hist_kernel<<<dim3(G, 2), TB>>>(nbr133, nbr313, n, HA, HB, MA, MB);
    scan_kernel<<<2, 512>>>(HA, HB);
    scatter_kernel<<<dim3(G, 2), TB>>>(MA, MB, n, HA, HB, PA, PB);

    // ===== ResContextBlock (16 -> 32) =====
    // c1 (x,133 -> BA) || c2 (x,313 -> BC)
    fused_conv_dual<16, 32, false, false><<<dim3(DB + SBX * 2, 2), TB, smem_fused(16, 32)>>>(
        x, nbr133, PA, HA, W_c1, nullptr, nullptr, BA,
        x, nbr313, PB, HB, W_c2, nullptr, nullptr, BC,
        n, ntiles, DB, SBX);
    // bn0 stats on BA -> SC0/SH0
    statsbn_kernel<32><<<148, 512>>>(BA, n, SUM + 0, SQ + 0, g0, b0, SC + 0, SH + 0, CTR + 0);
    // c12 (aff(BA),313 -> BB) || c3 (BC,133 -> BD)
    fused_conv_dual<32, 32, true, false><<<dim3(DB + SBX * 2, 2), TB, smem_fused(32, 32)>>>(
        BA, nbr313, PB, HB, W_c12, SC + 0, SH + 0, BB,
        BC, nbr133, PA, HA, W_c3, nullptr, nullptr, BD,
        n, ntiles, DB, SBX);
    // bn1 (BB) || bn2 (BD)
    statsbn_dual<32><<<dim3(148, 2), 512>>>(
        BB, SUM + 64,  SQ + 64,  g02, b02, SC + 64,  SH + 64,  CTR + 1,
        BD, SUM + 128, SQ + 128, g2,  b2,  SC + 128, SH + 128, CTR + 2, n);
    // y = bn2(BD) + bn1(BB) -> BC
    combine_kernel<32><<<(n * 32 + 255) / 256, 256>>>(BD, SC + 128, SH + 128,
                                                      BB, SC + 64,  SH + 64, BC, n * 32);

    // ===== ResBlock (32 -> 64) =====
    // r1 (BC,313 -> BA) || r2 (BC,133 -> BD)
    fused_conv_dual<32, 64, false, false><<<dim3(DB + SBX * 4, 2), TB, smem_fused(32, 64)>>>(
        BC, nbr313, PB, HB, W_r1, nullptr, nullptr, BA,
        BC, nbr133, PA, HA, W_r2, nullptr, nullptr, BD,
        n, ntiles, DB, SBX);
    // bn3 (BA) || bn5 (BD)
    statsbn_dual<64><<<dim3(148, 2), 512>>>(
        BA, SUM + 192, SQ + 192, rg0, rb0, SC + 192, SH + 192, CTR + 3,
        BD, SUM + 320, SQ + 320, rg1, rb1, SC + 320, SH + 320, CTR + 5, n);
    // r12 (aff(BA),133 -> BB) || r3 (aff(BD),313 -> BE)
    fused_conv_dual<64, 64, true, true><<<dim3(DB + SBX * 4, 2), TB, smem_fused(64, 64)>>>(
        BA, nbr133, PA, HA, W_r12, SC + 192, SH + 192, BB,
        BD, nbr313, PB, HB, W_r3,  SC + 320, SH + 320, BE,
        n, ntiles, DB, SBX);
    // bn4 (BB) || bn6 (BE)
    statsbn_dual<64><<<dim3(148, 2), 512>>>(
        BB, SUM + 256, SQ + 256, rg02, rb02, SC + 256, SH + 256, CTR + 4,
        BE, SUM + 384, SQ + 384, rg2,  rb2,  SC + 384, SH + 384, CTR + 6, n);
    // out = bn6(BE) + bn4(BB)
    combine_kernel<64><<<(n * 64 + 255) / 256, 256>>>(BE, SC + 384, SH + 384,
                                                      BB, SC + 256, SH + 256, out, n * 64);
}

// round 14
// speedup vs baseline: 3.3245x; 1.2627x over previous
#include <cuda_runtime.h>
#include <math.h>

#define NVOX 120000
#define EPSV 1e-5f

// ---------------- scratch (no dynamic alloc allowed) ----------------
__device__ __align__(16) float g_bufA[NVOX * 64];
__device__ __align__(16) float g_bufB[NVOX * 64];
__device__ __align__(16) float g_bufC[NVOX * 64];
__device__ __align__(16) float g_bufD[NVOX * 64];
__device__ __align__(16) float g_bufE[NVOX * 64];
__device__ float g_sum[7 * 64];
__device__ float g_sq [7 * 64];
__device__ int g_permA[NVOX];
__device__ int g_permB[NVOX];
__device__ int g_maskA[NVOX];
__device__ int g_maskB[NVOX];
__device__ int g_histA[512];
__device__ int g_histB[512];

// ---------------- packed f32x2 helpers ----------------
__device__ __forceinline__ unsigned long long pack2same(float v) {
    unsigned long long r;
    asm("mov.b64 %0, {%1, %1};" : "=l"(r) : "f"(v));
    return r;
}
__device__ __forceinline__ void unpack2(float& lo, float& hi, unsigned long long a) {
    asm("mov.b64 {%0, %1}, %2;" : "=f"(lo), "=f"(hi) : "l"(a));
}
__device__ __forceinline__ void ffma2(unsigned long long& d, unsigned long long a, unsigned long long b) {
    asm("fma.rn.f32x2 %0, %1, %2, %0;" : "+l"(d) : "l"(a), "l"(b));
}
__device__ __forceinline__ unsigned long long add2(unsigned long long a, unsigned long long b) {
    unsigned long long r;
    asm("add.rn.f32x2 %0, %1, %2;" : "=l"(r) : "l"(a), "l"(b));
    return r;
}
__device__ __forceinline__ unsigned long long mul2(unsigned long long a, unsigned long long b) {
    unsigned long long r;
    asm("mul.rn.f32x2 %0, %1, %2;" : "=l"(r) : "l"(a), "l"(b));
    return r;
}

template <int CT>
__device__ __forceinline__ void mac_row(unsigned long long* acc, float v, const float* w) {
    unsigned long long vv = pack2same(v);
    const ulonglong2* w2 = reinterpret_cast<const ulonglong2*>(w);
#pragma unroll
    for (int q = 0; q < CT / 4; q++) {
        ulonglong2 ww = w2[q];
        ffma2(acc[2 * q + 0], vv, ww.x);
        ffma2(acc[2 * q + 1], vv, ww.y);
    }
}

__device__ __forceinline__ float lrelu(float x) { return x > 0.f ? x : 0.01f * x; }

__device__ __forceinline__ float to_tf32(float x) {
    float r;
    asm("cvt.rna.tf32.f32 %0, %1;" : "=f"(r) : "f"(x));
    return r;
}

__device__ __forceinline__ void mma_tf32(float* c, const unsigned* a, unsigned b0, unsigned b1) {
    asm("mma.sync.aligned.m16n8k8.row.col.f32.tf32.tf32.f32 "
        "{%0,%1,%2,%3}, {%4,%5,%6,%7}, {%8,%9}, {%0,%1,%2,%3};"
        : "+f"(c[0]), "+f"(c[1]), "+f"(c[2]), "+f"(c[3])
        : "r"(a[0]), "r"(a[1]), "r"(a[2]), "r"(a[3]), "r"(b0), "r"(b1));
}

// ================= mask-bucket counting sort (both rulebooks) ==============
__global__ void mask_hist_kernel(const int* __restrict__ nbrA, const int* __restrict__ nbrB,
                                 int n, int* __restrict__ histA, int* __restrict__ histB,
                                 int* __restrict__ masksA, int* __restrict__ masksB) {
    const int* nbr = blockIdx.y ? nbrB : nbrA;
    int* hist      = blockIdx.y ? histB : histA;
    int* masks     = blockIdx.y ? masksB : masksA;
    __shared__ int lh[512];
    for (int i = threadIdx.x; i < 512; i += blockDim.x) lh[i] = 0;
    __syncthreads();
    int r = blockIdx.x * blockDim.x + threadIdx.x;
    if (r < n) {
        const int* nb = nbr + (size_t)r * 9;
        int m = 0;
#pragma unroll
        for (int k = 0; k < 9; k++) m |= (nb[k] < n) << k;
        masks[r] = m;
        atomicAdd(&lh[m], 1);
    }
    __syncthreads();
    for (int i = threadIdx.x; i < 512; i += blockDim.x)
        if (lh[i]) atomicAdd(&hist[i], lh[i]);
}

__global__ void scan_kernel(int* __restrict__ histA, int* __restrict__ histB) {
    int* hist = blockIdx.x ? histB : histA;
    __shared__ int tmp[512];
    int t = threadIdx.x;
    tmp[t] = hist[t];
    __syncthreads();
    for (int off = 1; off < 512; off <<= 1) {
        int add = (t >= off) ? tmp[t - off] : 0;
        __syncthreads();
        tmp[t] += add;
        __syncthreads();
    }
    hist[t] = (t == 0) ? 0 : tmp[t - 1];
}

__global__ void scatter_kernel(const int* __restrict__ masksA, const int* __restrict__ masksB,
                               int n, int* __restrict__ offsA, int* __restrict__ offsB,
                               int* __restrict__ permA, int* __restrict__ permB) {
    const int* masks = blockIdx.y ? masksB : masksA;
    int* offs        = blockIdx.y ? offsB : offsA;
    int* perm        = blockIdx.y ? permB : permA;
    int r = blockIdx.x * blockDim.x + threadIdx.x;
    int lane = threadIdx.x & 31;
    int m = (r < n) ? masks[r] : -1;
    unsigned grp = __match_any_sync(0xffffffffu, m);
    int leader = __ffs(grp) - 1;
    int rank = __popc(grp & ((1u << lane) - 1u));
    int base = 0;
    if (lane == leader && m >= 0) base = atomicAdd(&offs[m], __popc(grp));
    base = __shfl_sync(0xffffffffu, base, leader);
    if (m >= 0) perm[base + rank] = r;
}

// ============ conv body: dense tf32 GEMM + sparse fp32 gather ==============
// COMB: input = aff1(in) + aff2(in2). AFF: input = aff1(in). Affine params
// computed in prologue from producer stats (ps,pq) + g,b. STATS: fused
// per-channel sum/sumsq of lrelu output -> osum/osq (invalid rows give 0).
template <int CIN, int COUT, bool AFF, bool COMB, bool STATS>
__device__ __forceinline__ void
fused_conv_body(float* sm,
                const float* __restrict__ in, const float* __restrict__ in2,
                const int* __restrict__ nbr,
                const int* __restrict__ perm, const int* __restrict__ hist,
                const float* __restrict__ W,
                const float* __restrict__ ps1, const float* __restrict__ pq1,
                const float* __restrict__ g1, const float* __restrict__ b1,
                const float* __restrict__ ps2, const float* __restrict__ pq2,
                const float* __restrict__ g2, const float* __restrict__ b2,
                float* __restrict__ out, float* __restrict__ osum, float* __restrict__ osq,
                int n, int ntiles, int DB, int SBX) {
    const int tid = threadIdx.x;
    const int B16 = __ldg(hist + 16);
    const float inv_n = 1.0f / (float)n;

    if ((int)blockIdx.x < DB) {
        // ---------------- dense GEMM path ----------------
        constexpr int MX = (CIN > COUT) ? CIN : COUT;
        constexpr int SP = MX + 4;
        constexpr int WP = COUT + 1;
        float* wsm = sm;                    // CIN*WP (tf32)
        float* stg = wsm + CIN * WP;        // 8 warps * 16 * SP
        float* csc = stg + 8 * 16 * SP;     // CIN
        float* csh = csc + CIN;             // CIN
        float* csc2 = csh + CIN;            // CIN
        float* csh2 = csc2 + CIN;           // CIN
        const int wid = tid >> 5, lane = tid & 31;
        const int gr = lane >> 2, tg = lane & 3;

        if (AFF || COMB) {
            for (int i = tid; i < CIN; i += 256) {
                float m   = ps1[i] * inv_n;
                float var = pq1[i] * inv_n - m * m;
                float s   = g1[i] / sqrtf(var + EPSV);
                csc[i] = s; csh[i] = b1[i] - m * s;
            }
        }
        if (COMB) {
            for (int i = tid; i < CIN; i += 256) {
                float m   = ps2[i] * inv_n;
                float var = pq2[i] * inv_n - m * m;
                float s   = g2[i] / sqrtf(var + EPSV);
                csc2[i] = s; csh2[i] = b2[i] - m * s;
            }
        }
        {   // stage center weight slice (k=4), tf32-converted
            const float* Wc = W + 4 * CIN * COUT;
            for (int i = tid; i < CIN * COUT; i += 256) {
                int k = i / COUT, nn = i - k * COUT;
                wsm[k * WP + nn] = to_tf32(Wc[i]);
            }
        }
        __syncthreads();
        float* aw = stg + wid * 16 * SP;

        float s0 = 0.f, q0 = 0.f, s1 = 0.f, q1 = 0.f;

        for (int base = blockIdx.x * 128; base < B16; base += DB * 128) {
            const int wbase = base + wid * 16;
            if (wbase >= B16) continue;
            __syncwarp();
            int prow = -1;
            if (lane < 16 && wbase + lane < B16) prow = perm[wbase + lane];

#pragma unroll
            for (int it = 0; it < CIN / 8; it++) {
                int e = it * 32 + lane;
                int r = e / (CIN / 4), c4 = e - r * (CIN / 4);
                int pr = __shfl_sync(0xffffffffu, prow, r);
                float4 v = make_float4(0.f, 0.f, 0.f, 0.f);
                if (pr >= 0) {
                    v = *reinterpret_cast<const float4*>(in + (size_t)pr * CIN + 4 * c4);
                    if (AFF || COMB) {
                        v.x = fmaf(v.x, csc[4 * c4 + 0], csh[4 * c4 + 0]);
                        v.y = fmaf(v.y, csc[4 * c4 + 1], csh[4 * c4 + 1]);
                        v.z = fmaf(v.z, csc[4 * c4 + 2], csh[4 * c4 + 2]);
                        v.w = fmaf(v.w, csc[4 * c4 + 3], csh[4 * c4 + 3]);
                    }
                    if (COMB) {
                        float4 u = *reinterpret_cast<const float4*>(in2 + (size_t)pr * CIN + 4 * c4);
                        v.x += fmaf(u.x, csc2[4 * c4 + 0], csh2[4 * c4 + 0]);
                        v.y += fmaf(u.y, csc2[4 * c4 + 1], csh2[4 * c4 + 1]);
                        v.z += fmaf(u.z, csc2[4 * c4 + 2], csh2[4 * c4 + 2]);
                        v.w += fmaf(u.w, csc2[4 * c4 + 3], csh2[4 * c4 + 3]);
                    }
                }
                v.x = to_tf32(v.x); v.y = to_tf32(v.y); v.z = to_tf32(v.z); v.w = to_tf32(v.w);
                *reinterpret_cast<float4*>(aw + r * SP + 4 * c4) = v;
            }
            __syncwarp();

            unsigned af[CIN / 8][4];
#pragma unroll
            for (int kt = 0; kt < CIN / 8; kt++) {
                const float* r0 = aw + gr * SP + kt * 8 + tg;
                const float* r1 = aw + (gr + 8) * SP + kt * 8 + tg;
                af[kt][0] = __float_as_uint(r0[0]);
                af[kt][1] = __float_as_uint(r1[0]);
                af[kt][2] = __float_as_uint(r0[4]);
                af[kt][3] = __float_as_uint(r1[4]);
            }

            float cf[COUT / 8][4];
#pragma unroll
            for (int nt = 0; nt < COUT / 8; nt++) {
                cf[nt][0] = cf[nt][1] = cf[nt][2] = cf[nt][3] = 0.f;
#pragma unroll
                for (int kt = 0; kt < CIN / 8; kt++) {
                    unsigned b0 = __float_as_uint(wsm[(kt * 8 + tg) * WP + nt * 8 + gr]);
                    unsigned b1v = __float_as_uint(wsm[(kt * 8 + tg + 4) * WP + nt * 8 + gr]);
                    mma_tf32(cf[nt], af[kt], b0, b1v);
                }
            }
            __syncwarp();

#pragma unroll
            for (int nt = 0; nt < COUT / 8; nt++) {
                int col = nt * 8 + 2 * tg;
                aw[gr * SP + col]           = lrelu(cf[nt][0]);
                aw[gr * SP + col + 1]       = lrelu(cf[nt][1]);
                aw[(gr + 8) * SP + col]     = lrelu(cf[nt][2]);
                aw[(gr + 8) * SP + col + 1] = lrelu(cf[nt][3]);
            }
            __syncwarp();

            if (STATS) {
                // invalid rows hold exact zeros -> contribute nothing
#pragma unroll
                for (int r = 0; r < 16; r++) {
                    float v = aw[r * SP + lane];
                    s0 += v; q0 += v * v;
                    if (COUT == 64) {
                        float w = aw[r * SP + 32 + lane];
                        s1 += w; q1 += w * w;
                    }
                }
            }

#pragma unroll
            for (int it = 0; it < COUT / 8; it++) {
                int e = it * 32 + lane;
                int r = e / (COUT / 4), c4 = e - r * (COUT / 4);
                int pr = __shfl_sync(0xffffffffu, prow, r);
                if (pr >= 0)
                    *reinterpret_cast<float4*>(out + (size_t)pr * COUT + 4 * c4) =
                        *reinterpret_cast<const float4*>(aw + r * SP + 4 * c4);
            }
        }

        if (STATS) {
            atomicAdd(osum + lane, s0);
            atomicAdd(osq + lane, q0);
            if (COUT == 64) {
                atomicAdd(osum + 32 + lane, s1);
                atomicAdd(osq + 32 + lane, q1);
            }
        }
    } else {
        // ---------------- sparse gather path (CT = 16) ----------------
        constexpr int CT = 16;
        float* ws  = sm;                    // 9*CIN*CT
        float* csc = ws + 9 * CIN * CT;
        float* csh = csc + CIN;
        float* csc2 = csh + CIN;
        float* csh2 = csc2 + CIN;
        const int lane = tid & 31;
        const int s = blockIdx.x - DB;
        const int tbi = s / SBX;
        const int sx  = s - tbi * SBX;
        const int tb  = tbi * CT;

        {
            float4* ws4 = reinterpret_cast<float4*>(ws);
            const float4* W4 = reinterpret_cast<const float4*>(W);
            const int tb4 = tb >> 2;
            const int c4w = COUT >> 2;
            constexpr int TOT4 = 9 * CIN * CT / 4;
            constexpr int Q4 = CT / 4;
#pragma unroll 4
            for (int i = tid; i < TOT4; i += 256) {
                int r = i / Q4;
                int q = i - r * Q4;
                ws4[i] = W4[r * c4w + tb4 + q];
            }
        }
        if (AFF || COMB) {
            for (int i = tid; i < CIN; i += 256) {
                float m   = ps1[i] * inv_n;
                float var = pq1[i] * inv_n - m * m;
                float sc  = g1[i] / sqrtf(var + EPSV);
                csc[i] = sc; csh[i] = b1[i] - m * sc;
            }
        }
        if (COMB) {
            for (int i = tid; i < CIN; i += 256) {
                float m   = ps2[i] * inv_n;
                float var = pq2[i] * inv_n - m * m;
                float sc  = g2[i] / sqrtf(var + EPSV);
                csc2[i] = sc; csh2[i] = b2[i] - m * sc;
            }
        }
        __syncthreads();

        unsigned long long accS = 0ull, accQ = 0ull;
        const int t0 = B16 >> 8;
        for (int t = t0 + sx; t < ntiles; t += SBX) {
            const int gid = t * 256 + tid;
            const bool rok = (gid < n) && (gid >= B16);
            const int row = rok ? perm[gid] : 0;

            const int* nb = nbr + (size_t)row * 9;
            int idx[9];
#pragma unroll
            for (int k = 0; k < 9; k++) idx[k] = rok ? __ldg(nb + k) : n;

            unsigned long long acc[CT / 2];
#pragma unroll
            for (int i = 0; i < CT / 2; i++) acc[i] = 0ull;

#pragma unroll
            for (int k = 0; k < 9; k++) {
                const int j = idx[k];
                const bool v = j < n;
                if (!__any_sync(0xffffffffu, v)) continue;
                const float4* xr = reinterpret_cast<const float4*>(in + (size_t)j * CIN);
                const float4* xr2 = COMB ? reinterpret_cast<const float4*>(in2 + (size_t)j * CIN) : nullptr;
                const float* wk = ws + k * CIN * CT;
#pragma unroll
                for (int c4 = 0; c4 < CIN / 4; c4++) {
                    float4 val = make_float4(0.f, 0.f, 0.f, 0.f);
                    if (v) {
                        val = xr[c4];
                        if (AFF || COMB) {
                            val.x = fmaf(val.x, csc[4 * c4 + 0], csh[4 * c4 + 0]);
                            val.y = fmaf(val.y, csc[4 * c4 + 1], csh[4 * c4 + 1]);
                            val.z = fmaf(val.z, csc[4 * c4 + 2], csh[4 * c4 + 2]);
                            val.w = fmaf(val.w, csc[4 * c4 + 3], csh[4 * c4 + 3]);
                        }
                        if (COMB) {
                            float4 u = xr2[c4];
                            val.x += fmaf(u.x, csc2[4 * c4 + 0], csh2[4 * c4 + 0]);
                            val.y += fmaf(u.y, csc2[4 * c4 + 1], csh2[4 * c4 + 1]);
                            val.z += fmaf(u.z, csc2[4 * c4 + 2], csh2[4 * c4 + 2]);
                            val.w += fmaf(u.w, csc2[4 * c4 + 3], csh2[4 * c4 + 3]);
                        }
                    }
                    const float* w0 = wk + (4 * c4) * CT;
                    mac_row<CT>(acc, val.x, w0);
                    mac_row<CT>(acc, val.y, w0 + CT);
                    mac_row<CT>(acc, val.z, w0 + 2 * CT);
                    mac_row<CT>(acc, val.w, w0 + 3 * CT);
                }
            }

            // lrelu, store, butterfly-stats (invalid rows -> zeros)
            float* o = out + (size_t)row * COUT + tb;
#pragma unroll
            for (int i = 0; i < CT / 2; i++) {
                float lo, hi;
                unpack2(lo, hi, acc[i]);
                lo = lrelu(lo); hi = lrelu(hi);
                unsigned long long pv;
                asm("mov.b64 %0, {%1, %2};" : "=l"(pv) : "f"(lo), "f"(hi));
                acc[i] = pv;
                if (rok) reinterpret_cast<float2*>(o)[i] = make_float2(lo, hi);
            }

            if (STATS) {
#pragma unroll
                for (int i = 0; i < CT / 2; i++) {
                    unsigned long long v = acc[i];
                    unsigned long long q = mul2(v, v);
#pragma unroll
                    for (int m = 16; m; m >>= 1) {
                        v = add2(v, __shfl_xor_sync(0xffffffffu, v, m));
                        q = add2(q, __shfl_xor_sync(0xffffffffu, q, m));
                    }
                    if (lane == i) accS = add2(accS, v);
                    if (lane == 16 + i) accQ = add2(accQ, q);
                }
            }
        }

        if (STATS) {
            if (lane < 8) {
                float lo, hi;
                unpack2(lo, hi, accS);
                atomicAdd(osum + tb + 2 * lane, lo);
                atomicAdd(osum + tb + 2 * lane + 1, hi);
            }
            if (lane >= 16 && lane < 24) {
                float lo, hi;
                unpack2(lo, hi, accQ);
                atomicAdd(osq + tb + 2 * (lane - 16), lo);
                atomicAdd(osq + tb + 2 * (lane - 16) + 1, hi);
            }
        }
    }
}

// dual-problem wrapper: blockIdx.y selects the conv problem
template <int CIN, int COUT, bool AF1, bool CB1, bool ST1, bool AF2, bool CB2, bool ST2>
__global__ void __launch_bounds__(256)
fused_conv_dual(const float* in1, const float* in1b, const int* nbr1, const int* perm1, const int* hist1,
                const float* W1, const float* ps1a, const float* pq1a, const float* g1a, const float* b1a,
                const float* ps1b, const float* pq1b, const float* g1b, const float* b1b,
                float* out1, float* osum1, float* osq1,
                const float* in2, const float* in2b, const int* nbr2, const int* perm2, const int* hist2,
                const float* W2, const float* ps2a, const float* pq2a, const float* g2a, const float* b2a,
                const float* ps2b, const float* pq2b, const float* g2b, const float* b2b,
                float* out2, float* osum2, float* osq2,
                int n, int ntiles, int DB, int SBX) {
    extern __shared__ __align__(16) float sm[];
    if (blockIdx.y == 0)
        fused_conv_body<CIN, COUT, AF1, CB1, ST1>(sm, in1, in1b, nbr1, perm1, hist1, W1,
            ps1a, pq1a, g1a, b1a, ps1b, pq1b, g1b, b1b, out1, osum1, osq1, n, ntiles, DB, SBX);
    else
        fused_conv_body<CIN, COUT, AF2, CB2, ST2>(sm, in2, in2b, nbr2, perm2, hist2, W2,
            ps2a, pq2a, g2a, b2a, ps2b, pq2b, g2b, b2b, out2, osum2, osq2, n, ntiles, DB, SBX);
}

// ---------------- out = bnA(a) + bnB(b); bn from SUM/SQ in prologue --------
template <int C>
__global__ void combine_kernel(const float* __restrict__ a,
                               const float* __restrict__ suma, const float* __restrict__ sqa,
                               const float* __restrict__ ga, const float* __restrict__ ba,
                               const float* __restrict__ bsrc,
                               const float* __restrict__ sumb, const float* __restrict__ sqb,
                               const float* __restrict__ gb, const float* __restrict__ bb,
                               float* __restrict__ o, int n) {
    __shared__ float sA[C], hA[C], sB[C], hB[C];
    const float inv_n = 1.0f / (float)n;
    for (int i = threadIdx.x; i < C; i += blockDim.x) {
        float m   = suma[i] * inv_n;
        float var = sqa[i] * inv_n - m * m;
        float s   = ga[i] / sqrtf(var + EPSV);
        sA[i] = s; hA[i] = ba[i] - m * s;
        m   = sumb[i] * inv_n;
        var = sqb[i] * inv_n - m * m;
        s   = gb[i] / sqrtf(var + EPSV);
        sB[i] = s; hB[i] = bb[i] - m * s;
    }
    __syncthreads();
    const int total = n * C;
    for (int i = blockIdx.x * blockDim.x + threadIdx.x; i < total; i += gridDim.x * blockDim.x) {
        int c = i & (C - 1);
        o[i] = fmaf(a[i], sA[c], hA[c]) + fmaf(bsrc[i], sB[c], hB[c]);
    }
}

__global__ void zero_kernel(float* __restrict__ sum, float* __restrict__ sq,
                            int* __restrict__ hA, int* __restrict__ hB) {
    int i = blockIdx.x * blockDim.x + threadIdx.x;
    if (i < 7 * 64) { sum[i] = 0.f; sq[i] = 0.f; }
    if (i < 512) { hA[i] = 0; hB[i] = 0; }
}

// ---------------- host ----------------
static constexpr size_t smem_fused(int cin, int cout) {
    int mx = cin > cout ? cin : cout;
    size_t gemm = (size_t)(cin * (cout + 1) + 8 * 16 * (mx + 4) + 4 * cin) * sizeof(float);
    size_t sparse = (size_t)(9 * cin * 16 + 4 * cin) * sizeof(float);
    return gemm > sparse ? gemm : sparse;
}

extern "C" void kernel_launch(void* const* d_in, const int* in_sizes, int n_in,
                              void* d_out, int out_size) {
    const float* x      = (const float*)d_in[0];
    const int*   nbr133 = (const int*)  d_in[1];
    const int*   nbr313 = (const int*)  d_in[2];
    const float* W_c1   = (const float*)d_in[3];
    const float* g0     = (const float*)d_in[4];
    const float* b0     = (const float*)d_in[5];
    const float* W_c12  = (const float*)d_in[6];
    const float* g02    = (const float*)d_in[7];
    const float* b02    = (const float*)d_in[8];
    const float* W_c2   = (const float*)d_in[9];
    const float* W_c3   = (const float*)d_in[10];
    const float* g2     = (const float*)d_in[11];
    const float* b2     = (const float*)d_in[12];
    const float* W_r1   = (const float*)d_in[13];
    const float* rg0    = (const float*)d_in[14];
    const float* rb0    = (const float*)d_in[15];
    const float* W_r12  = (const float*)d_in[16];
    const float* rg02   = (const float*)d_in[17];
    const float* rb02   = (const float*)d_in[18];
    const float* W_r2   = (const float*)d_in[19];
    const float* rg1    = (const float*)d_in[20];
    const float* rb1    = (const float*)d_in[21];
    const float* W_r3   = (const float*)d_in[22];
    const float* rg2    = (const float*)d_in[23];
    const float* rb2    = (const float*)d_in[24];
    float* out = (float*)d_out;

    const int n = in_sizes[0] / 16;   // 120000

    float *BA, *BB, *BC, *BD, *BE, *SUM, *SQ;
    int *PA, *PB, *MA, *MB, *HA, *HB;
    cudaGetSymbolAddress((void**)&BA,  g_bufA);
    cudaGetSymbolAddress((void**)&BB,  g_bufB);
    cudaGetSymbolAddress((void**)&BC,  g_bufC);
    cudaGetSymbolAddress((void**)&BD,  g_bufD);
    cudaGetSymbolAddress((void**)&BE,  g_bufE);
    cudaGetSymbolAddress((void**)&SUM, g_sum);
    cudaGetSymbolAddress((void**)&SQ,  g_sq);
    cudaGetSymbolAddress((void**)&PA,  g_permA);
    cudaGetSymbolAddress((void**)&PB,  g_permB);
    cudaGetSymbolAddress((void**)&MA,  g_maskA);
    cudaGetSymbolAddress((void**)&MB,  g_maskB);
    cudaGetSymbolAddress((void**)&HA,  g_histA);
    cudaGetSymbolAddress((void**)&HB,  g_histB);

    static int inited = 0;
    if (!inited) {
        inited = 1;
        cudaFuncSetAttribute((const void*)fused_conv_dual<64, 64, true, false, true, true, false, true>,
                             cudaFuncAttributeMaxDynamicSharedMemorySize, (int)smem_fused(64, 64));
        cudaFuncSetAttribute((const void*)fused_conv_dual<32, 64, false, true, true, false, true, true>,
                             cudaFuncAttributeMaxDynamicSharedMemorySize, (int)smem_fused(32, 64));
    }

    const int TB = 256;
    const int ntiles = (n + TB - 1) / TB;
    const int G = ntiles;
    const int DB  = 148;   // dense gemm blocks per problem slice
    const int SBX = 64;    // sparse blocks per COUT tile per slice

    // ----- prologue (4 nodes) -----
    zero_kernel<<<2, 512>>>(SUM, SQ, HA, HB);
    mask_hist_kernel<<<dim3(G, 2), TB>>>(nbr133, nbr313, n, HA, HB, MA, MB);
    scan_kernel<<<2, 512>>>(HA, HB);
    scatter_kernel<<<dim3(G, 2), TB>>>(MA, MB, n, HA, HB, PA, PB);

    // ===== node 5: c1 (x,133 -> BA, stats SUM0) || c2 (x,313 -> BC) =====
    fused_conv_dual<16, 32, false, false, true, false, false, false>
        <<<dim3(DB + SBX * 2, 2), TB, smem_fused(16, 32)>>>(
        x, nullptr, nbr133, PA, HA, W_c1,
        nullptr, nullptr, nullptr, nullptr, nullptr, nullptr, nullptr, nullptr,
        BA, SUM + 0, SQ + 0,
        x, nullptr, nbr313, PB, HB, W_c2,
        nullptr, nullptr, nullptr, nullptr, nullptr, nullptr, nullptr, nullptr,
        BC, nullptr, nullptr,
        n, ntiles, DB, SBX);

    // ===== node 6: c12 (aff0(BA),313 -> BB, stats SUM64) || c3 (BC,133 -> BD, stats SUM128) =====
    fused_conv_dual<32, 32, true, false, true, false, false, true>
        <<<dim3(DB + SBX * 2, 2), TB, smem_fused(32, 32)>>>(
        BA, nullptr, nbr313, PB, HB, W_c12,
        SUM + 0, SQ + 0, g0, b0, nullptr, nullptr, nullptr, nullptr,
        BB, SUM + 64, SQ + 64,
        BC, nullptr, nbr133, PA, HA, W_c3,
        nullptr, nullptr, nullptr, nullptr, nullptr, nullptr, nullptr, nullptr,
        BD, SUM + 128, SQ + 128,
        n, ntiles, DB, SBX);

    // ===== node 7: y = bn2(BD)+bn1(BB) fused into r1/r2 gather =====
    // r1 (y,313 -> BA, stats SUM192) || r2 (y,133 -> BE, stats SUM320)
    fused_conv_dual<32, 64, false, true, true, false, true, true>
        <<<dim3(DB + SBX * 4, 2), TB, smem_fused(32, 64)>>>(
        BD, BB, nbr313, PB, HB, W_r1,
        SUM + 128, SQ + 128, g2, b2, SUM + 64, SQ + 64, g02, b02,
        BA, SUM + 192, SQ + 192,
        BD, BB, nbr133, PA, HA, W_r2,
        SUM + 128, SQ + 128, g2, b2, SUM + 64, SQ + 64, g02, b02,
        BE, SUM + 320, SQ + 320,
        n, ntiles, DB, SBX);

    // ===== node 8: r12 (aff3(BA),133 -> BB, stats SUM256) || r3 (aff5(BE),313 -> BD, stats SUM384) =====
    fused_conv_dual<64, 64, true, false, true, true, false, true>
        <<<dim3(DB + SBX * 4, 2), TB, smem_fused(64, 64)>>>(
        BA, nullptr, nbr133, PA, HA, W_r12,
        SUM + 192, SQ + 192, rg0, rb0, nullptr, nullptr, nullptr, nullptr,
        BB, SUM + 256, SQ + 256,
        BE, nullptr, nbr313, PB, HB, W_r3,
        SUM + 320, SQ + 320, rg1, rb1, nullptr, nullptr, nullptr, nullptr,
        BD, SUM + 384, SQ + 384,
        n, ntiles, DB, SBX);

    // ===== node 9: out = bn6(BD) + bn4(BB) =====
    combine_kernel<64><<<1184, 256>>>(BD, SUM + 384, SQ + 384, rg2, rb2,
                                      BB, SUM + 256, SQ + 256, rg02, rb02, out, n);
}

// round 16
// speedup vs baseline: 3.3726x; 1.0145x over previous
#include <cuda_runtime.h>
#include <math.h>

#define NVOX 120000
#define EPSV 1e-5f

// ---------------- scratch (no dynamic alloc allowed) ----------------
__device__ __align__(16) float g_bufA[NVOX * 64];
__device__ __align__(16) float g_bufB[NVOX * 64];
__device__ __align__(16) float g_bufC[NVOX * 64];
__device__ __align__(16) float g_bufD[NVOX * 64];
__device__ __align__(16) float g_bufE[NVOX * 64];
__device__ float g_sum[7 * 64];
__device__ float g_sq [7 * 64];
__device__ int g_permA[NVOX];
__device__ int g_permB[NVOX];
__device__ int g_maskA[NVOX];
__device__ int g_maskB[NVOX];
__device__ int g_histA[512];
__device__ int g_histB[512];
__device__ int g_ctrA[512];
__device__ int g_ctrB[512];

// ---------------- packed f32x2 helpers ----------------
__device__ __forceinline__ unsigned long long pack2same(float v) {
    unsigned long long r;
    asm("mov.b64 %0, {%1, %1};" : "=l"(r) : "f"(v));
    return r;
}
__device__ __forceinline__ void unpack2(float& lo, float& hi, unsigned long long a) {
    asm("mov.b64 {%0, %1}, %2;" : "=f"(lo), "=f"(hi) : "l"(a));
}
__device__ __forceinline__ void ffma2(unsigned long long& d, unsigned long long a, unsigned long long b) {
    asm("fma.rn.f32x2 %0, %1, %2, %0;" : "+l"(d) : "l"(a), "l"(b));
}
__device__ __forceinline__ unsigned long long add2(unsigned long long a, unsigned long long b) {
    unsigned long long r;
    asm("add.rn.f32x2 %0, %1, %2;" : "=l"(r) : "l"(a), "l"(b));
    return r;
}
__device__ __forceinline__ unsigned long long mul2(unsigned long long a, unsigned long long b) {
    unsigned long long r;
    asm("mul.rn.f32x2 %0, %1, %2;" : "=l"(r) : "l"(a), "l"(b));
    return r;
}

template <int CT>
__device__ __forceinline__ void mac_row(unsigned long long* acc, float v, const float* w) {
    unsigned long long vv = pack2same(v);
    const ulonglong2* w2 = reinterpret_cast<const ulonglong2*>(w);
#pragma unroll
    for (int q = 0; q < CT / 4; q++) {
        ulonglong2 ww = w2[q];
        ffma2(acc[2 * q + 0], vv, ww.x);
        ffma2(acc[2 * q + 1], vv, ww.y);
    }
}

__device__ __forceinline__ float lrelu(float x) { return x > 0.f ? x : 0.01f * x; }

__device__ __forceinline__ float to_tf32(float x) {
    float r;
    asm("cvt.rna.tf32.f32 %0, %1;" : "=f"(r) : "f"(x));
    return r;
}

__device__ __forceinline__ void mma_tf32(float* c, const unsigned* a, unsigned b0, unsigned b1) {
    asm("mma.sync.aligned.m16n8k8.row.col.f32.tf32.tf32.f32 "
        "{%0,%1,%2,%3}, {%4,%5,%6,%7}, {%8,%9}, {%0,%1,%2,%3};"
        : "+f"(c[0]), "+f"(c[1]), "+f"(c[2]), "+f"(c[3])
        : "r"(a[0]), "r"(a[1]), "r"(a[2]), "r"(a[3]), "r"(b0), "r"(b1));
}

// ================= node 1: mask histogram (+ zero SUM/SQ) ==================
// hist/ctr are zeroed by the LAST node of the previous call/replay (combine),
// so this launch accumulates into clean arrays. Block (0,0) zeroes SUM/SQ —
// safe: their writers (convs) are later in this replay's chain; their readers
// from the previous replay finished before this replay started.
__global__ void mask_hist_kernel(const int* __restrict__ nbrA, const int* __restrict__ nbrB,
                                 int n, int* __restrict__ histA, int* __restrict__ histB,
                                 int* __restrict__ masksA, int* __restrict__ masksB,
                                 float* __restrict__ sum, float* __restrict__ sq) {
    if (blockIdx.x == 0 && blockIdx.y == 0) {
        for (int i = threadIdx.x; i < 7 * 64; i += blockDim.x) { sum[i] = 0.f; sq[i] = 0.f; }
    }
    const int* nbr = blockIdx.y ? nbrB : nbrA;
    int* hist      = blockIdx.y ? histB : histA;
    int* masks     = blockIdx.y ? masksB : masksA;
    __shared__ int lh[512];
    for (int i = threadIdx.x; i < 512; i += blockDim.x) lh[i] = 0;
    __syncthreads();
    int r = blockIdx.x * blockDim.x + threadIdx.x;
    if (r < n) {
        const int* nb = nbr + (size_t)r * 9;
        int m = 0;
#pragma unroll
        for (int k = 0; k < 9; k++) m |= (nb[k] < n) << k;
        masks[r] = m;
        atomicAdd(&lh[m], 1);
    }
    __syncthreads();
    for (int i = threadIdx.x; i < 512; i += blockDim.x)
        if (lh[i]) atomicAdd(&hist[i], lh[i]);
}

// ================= node 2: scatter with block-local scan ===================
// Each block re-computes the exclusive scan of the raw hist in smem, then
// places rows at scan[m] + atomicAdd(ctr[m], cnt). 512 threads.
__global__ void scatter_kernel(const int* __restrict__ masksA, const int* __restrict__ masksB,
                               int n, const int* __restrict__ histA, const int* __restrict__ histB,
                               int* __restrict__ ctrA, int* __restrict__ ctrB,
                               int* __restrict__ permA, int* __restrict__ permB) {
    const int* masks = blockIdx.y ? masksB : masksA;
    const int* hist  = blockIdx.y ? histB : histA;
    int* ctr         = blockIdx.y ? ctrB : ctrA;
    int* perm        = blockIdx.y ? permB : permA;
    __shared__ int tmp[512];
    __shared__ int sc[512];
    int t = threadIdx.x;
    tmp[t] = hist[t];
    __syncthreads();
    for (int off = 1; off < 512; off <<= 1) {
        int add = (t >= off) ? tmp[t - off] : 0;
        __syncthreads();
        tmp[t] += add;
        __syncthreads();
    }
    sc[t] = (t == 0) ? 0 : tmp[t - 1];
    __syncthreads();

    int r = blockIdx.x * 512 + t;
    int lane = t & 31;
    int m = (r < n) ? masks[r] : -1;
    unsigned grp = __match_any_sync(0xffffffffu, m);
    int leader = __ffs(grp) - 1;
    int rank = __popc(grp & ((1u << lane) - 1u));
    int base = 0;
    if (lane == leader && m >= 0) base = sc[m] + atomicAdd(&ctr[m], __popc(grp));
    base = __shfl_sync(0xffffffffu, base, leader);
    if (m >= 0) perm[base + rank] = r;
}

// ============ conv body: dense tf32 GEMM + sparse fp32 gather ==============
// COMB: input = aff1(in) + aff2(in2). AFF: input = aff1(in). Affine params
// computed in prologue from producer stats (ps,pq) + g,b. STATS: fused
// per-channel sum/sumsq of lrelu output -> osum/osq (invalid rows give 0).
// hist[16] = count of center-only rows (raw histogram; masks always >= 16).
template <int CIN, int COUT, bool AFF, bool COMB, bool STATS>
__device__ __forceinline__ void
fused_conv_body(float* sm,
                const float* __restrict__ in, const float* __restrict__ in2,
                const int* __restrict__ nbr,
                const int* __restrict__ perm, const int* __restrict__ hist,
                const float* __restrict__ W,
                const float* __restrict__ ps1, const float* __restrict__ pq1,
                const float* __restrict__ g1, const float* __restrict__ b1,
                const float* __restrict__ ps2, const float* __restrict__ pq2,
                const float* __restrict__ g2, const float* __restrict__ b2,
                float* __restrict__ out, float* __restrict__ osum, float* __restrict__ osq,
                int n, int ntiles, int DB, int SBX) {
    const int tid = threadIdx.x;
    const int B16 = __ldg(hist + 16);
    const float inv_n = 1.0f / (float)n;

    if ((int)blockIdx.x < DB) {
        // ---------------- dense GEMM path ----------------
        constexpr int MX = (CIN > COUT) ? CIN : COUT;
        constexpr int SP = MX + 4;
        constexpr int WP = COUT + 1;
        float* wsm = sm;                    // CIN*WP (tf32)
        float* stg = wsm + CIN * WP;        // 8 warps * 16 * SP
        float* csc = stg + 8 * 16 * SP;     // CIN
        float* csh = csc + CIN;             // CIN
        float* csc2 = csh + CIN;            // CIN
        float* csh2 = csc2 + CIN;           // CIN
        const int wid = tid >> 5, lane = tid & 31;
        const int gr = lane >> 2, tg = lane & 3;

        if (AFF || COMB) {
            for (int i = tid; i < CIN; i += 256) {
                float m   = ps1[i] * inv_n;
                float var = pq1[i] * inv_n - m * m;
                float s   = g1[i] / sqrtf(var + EPSV);
                csc[i] = s; csh[i] = b1[i] - m * s;
            }
        }
        if (COMB) {
            for (int i = tid; i < CIN; i += 256) {
                float m   = ps2[i] * inv_n;
                float var = pq2[i] * inv_n - m * m;
                float s   = g2[i] / sqrtf(var + EPSV);
                csc2[i] = s; csh2[i] = b2[i] - m * s;
            }
        }
        {   // stage center weight slice (k=4), tf32-converted
            const float* Wc = W + 4 * CIN * COUT;
            for (int i = tid; i < CIN * COUT; i += 256) {
                int k = i / COUT, nn = i - k * COUT;
                wsm[k * WP + nn] = to_tf32(Wc[i]);
            }
        }
        __syncthreads();
        float* aw = stg + wid * 16 * SP;

        float s0 = 0.f, q0 = 0.f, s1 = 0.f, q1 = 0.f;

        for (int base = blockIdx.x * 128; base < B16; base += DB * 128) {
            const int wbase = base + wid * 16;
            if (wbase >= B16) continue;
            __syncwarp();
            int prow = -1;
            if (lane < 16 && wbase + lane < B16) prow = perm[wbase + lane];

#pragma unroll
            for (int it = 0; it < CIN / 8; it++) {
                int e = it * 32 + lane;
                int r = e / (CIN / 4), c4 = e - r * (CIN / 4);
                int pr = __shfl_sync(0xffffffffu, prow, r);
                float4 v = make_float4(0.f, 0.f, 0.f, 0.f);
                if (pr >= 0) {
                    v = *reinterpret_cast<const float4*>(in + (size_t)pr * CIN + 4 * c4);
                    if (AFF || COMB) {
                        v.x = fmaf(v.x, csc[4 * c4 + 0], csh[4 * c4 + 0]);
                        v.y = fmaf(v.y, csc[4 * c4 + 1], csh[4 * c4 + 1]);
                        v.z = fmaf(v.z, csc[4 * c4 + 2], csh[4 * c4 + 2]);
                        v.w = fmaf(v.w, csc[4 * c4 + 3], csh[4 * c4 + 3]);
                    }
                    if (COMB) {
                        float4 u = *reinterpret_cast<const float4*>(in2 + (size_t)pr * CIN + 4 * c4);
                        v.x += fmaf(u.x, csc2[4 * c4 + 0], csh2[4 * c4 + 0]);
                        v.y += fmaf(u.y, csc2[4 * c4 + 1], csh2[4 * c4 + 1]);
                        v.z += fmaf(u.z, csc2[4 * c4 + 2], csh2[4 * c4 + 2]);
                        v.w += fmaf(u.w, csc2[4 * c4 + 3], csh2[4 * c4 + 3]);
                    }
                }
                v.x = to_tf32(v.x); v.y = to_tf32(v.y); v.z = to_tf32(v.z); v.w = to_tf32(v.w);
                *reinterpret_cast<float4*>(aw + r * SP + 4 * c4) = v;
            }
            __syncwarp();

            unsigned af[CIN / 8][4];
#pragma unroll
            for (int kt = 0; kt < CIN / 8; kt++) {
                const float* r0 = aw + gr * SP + kt * 8 + tg;
                const float* r1 = aw + (gr + 8) * SP + kt * 8 + tg;
                af[kt][0] = __float_as_uint(r0[0]);
                af[kt][1] = __float_as_uint(r1[0]);
                af[kt][2] = __float_as_uint(r0[4]);
                af[kt][3] = __float_as_uint(r1[4]);
            }

            float cf[COUT / 8][4];
#pragma unroll
            for (int nt = 0; nt < COUT / 8; nt++) {
                cf[nt][0] = cf[nt][1] = cf[nt][2] = cf[nt][3] = 0.f;
#pragma unroll
                for (int kt = 0; kt < CIN / 8; kt++) {
                    unsigned b0 = __float_as_uint(wsm[(kt * 8 + tg) * WP + nt * 8 + gr]);
                    unsigned b1v = __float_as_uint(wsm[(kt * 8 + tg + 4) * WP + nt * 8 + gr]);
                    mma_tf32(cf[nt], af[kt], b0, b1v);
                }
            }
            __syncwarp();

#pragma unroll
            for (int nt = 0; nt < COUT / 8; nt++) {
                int col = nt * 8 + 2 * tg;
                aw[gr * SP + col]           = lrelu(cf[nt][0]);
                aw[gr * SP + col + 1]       = lrelu(cf[nt][1]);
                aw[(gr + 8) * SP + col]     = lrelu(cf[nt][2]);
                aw[(gr + 8) * SP + col + 1] = lrelu(cf[nt][3]);
            }
            __syncwarp();

            if (STATS) {
                // invalid rows hold exact zeros -> contribute nothing
#pragma unroll
                for (int r = 0; r < 16; r++) {
                    float v = aw[r * SP + lane];
                    s0 += v; q0 += v * v;
                    if (COUT == 64) {
                        float w = aw[r * SP + 32 + lane];
                        s1 += w; q1 += w * w;
                    }
                }
            }

#pragma unroll
            for (int it = 0; it < COUT / 8; it++) {
                int e = it * 32 + lane;
                int r = e / (COUT / 4), c4 = e - r * (COUT / 4);
                int pr = __shfl_sync(0xffffffffu, prow, r);
                if (pr >= 0)
                    *reinterpret_cast<float4*>(out + (size_t)pr * COUT + 4 * c4) =
                        *reinterpret_cast<const float4*>(aw + r * SP + 4 * c4);
            }
        }

        if (STATS) {
            atomicAdd(osum + lane, s0);
            atomicAdd(osq + lane, q0);
            if (COUT == 64) {
                atomicAdd(osum + 32 + lane, s1);
                atomicAdd(osq + 32 + lane, q1);
            }
        }
    } else {
        // ---------------- sparse gather path (CT = 16) ----------------
        constexpr int CT = 16;
        float* ws  = sm;                    // 9*CIN*CT
        float* csc = ws + 9 * CIN * CT;
        float* csh = csc + CIN;
        float* csc2 = csh + CIN;
        float* csh2 = csc2 + CIN;
        const int lane = tid & 31;
        const int s = blockIdx.x - DB;
        const int tbi = s / SBX;
        const int sx  = s - tbi * SBX;
        const int tb  = tbi * CT;

        {
            float4* ws4 = reinterpret_cast<float4*>(ws);
            const float4* W4 = reinterpret_cast<const float4*>(W);
            const int tb4 = tb >> 2;
            const int c4w = COUT >> 2;
            constexpr int TOT4 = 9 * CIN * CT / 4;
            constexpr int Q4 = CT / 4;
#pragma unroll 4
            for (int i = tid; i < TOT4; i += 256) {
                int r = i / Q4;
                int q = i - r * Q4;
                ws4[i] = W4[r * c4w + tb4 + q];
            }
        }
        if (AFF || COMB) {
            for (int i = tid; i < CIN; i += 256) {
                float m   = ps1[i] * inv_n;
                float var = pq1[i] * inv_n - m * m;
                float sc  = g1[i] / sqrtf(var + EPSV);
                csc[i] = sc; csh[i] = b1[i] - m * sc;
            }
        }
        if (COMB) {
            for (int i = tid; i < CIN; i += 256) {
                float m   = ps2[i] * inv_n;
                float var = pq2[i] * inv_n - m * m;
                float sc  = g2[i] / sqrtf(var + EPSV);
                csc2[i] = sc; csh2[i] = b2[i] - m * sc;
            }
        }
        __syncthreads();

        unsigned long long accS = 0ull, accQ = 0ull;
        const int t0 = B16 >> 8;
        for (int t = t0 + sx; t < ntiles; t += SBX) {
            const int gid = t * 256 + tid;
            const bool rok = (gid < n) && (gid >= B16);
            const int row = rok ? perm[gid] : 0;

            const int* nb = nbr + (size_t)row * 9;
            int idx[9];
#pragma unroll
            for (int k = 0; k < 9; k++) idx[k] = rok ? __ldg(nb + k) : n;

            unsigned long long acc[CT / 2];
#pragma unroll
            for (int i = 0; i < CT / 2; i++) acc[i] = 0ull;

#pragma unroll
            for (int k = 0; k < 9; k++) {
                const int j = idx[k];
                const bool v = j < n;
                if (!__any_sync(0xffffffffu, v)) continue;
                const float4* xr = reinterpret_cast<const float4*>(in + (size_t)j * CIN);
                const float4* xr2 = COMB ? reinterpret_cast<const float4*>(in2 + (size_t)j * CIN) : nullptr;
                const float* wk = ws + k * CIN * CT;
#pragma unroll
                for (int c4 = 0; c4 < CIN / 4; c4++) {
                    float4 val = make_float4(0.f, 0.f, 0.f, 0.f);
                    if (v) {
                        val = xr[c4];
                        if (AFF || COMB) {
                            val.x = fmaf(val.x, csc[4 * c4 + 0], csh[4 * c4 + 0]);
                            val.y = fmaf(val.y, csc[4 * c4 + 1], csh[4 * c4 + 1]);
                            val.z = fmaf(val.z, csc[4 * c4 + 2], csh[4 * c4 + 2]);
                            val.w = fmaf(val.w, csc[4 * c4 + 3], csh[4 * c4 + 3]);
                        }
                        if (COMB) {
                            float4 u = xr2[c4];
                            val.x += fmaf(u.x, csc2[4 * c4 + 0], csh2[4 * c4 + 0]);
                            val.y += fmaf(u.y, csc2[4 * c4 + 1], csh2[4 * c4 + 1]);
                            val.z += fmaf(u.z, csc2[4 * c4 + 2], csh2[4 * c4 + 2]);
                            val.w += fmaf(u.w, csc2[4 * c4 + 3], csh2[4 * c4 + 3]);
                        }
                    }
                    const float* w0 = wk + (4 * c4) * CT;
                    mac_row<CT>(acc, val.x, w0);
                    mac_row<CT>(acc, val.y, w0 + CT);
                    mac_row<CT>(acc, val.z, w0 + 2 * CT);
                    mac_row<CT>(acc, val.w, w0 + 3 * CT);
                }
            }

            // lrelu, store, butterfly-stats (invalid rows -> zeros)
            float* o = out + (size_t)row * COUT + tb;
#pragma unroll
            for (int i = 0; i < CT / 2; i++) {
                float lo, hi;
                unpack2(lo, hi, acc[i]);
                lo = lrelu(lo); hi = lrelu(hi);
                unsigned long long pv;
                asm("mov.b64 %0, {%1, %2};" : "=l"(pv) : "f"(lo), "f"(hi));
                acc[i] = pv;
                if (rok) reinterpret_cast<float2*>(o)[i] = make_float2(lo, hi);
            }

            if (STATS) {
#pragma unroll
                for (int i = 0; i < CT / 2; i++) {
                    unsigned long long v = acc[i];
                    unsigned long long q = mul2(v, v);
#pragma unroll
                    for (int m = 16; m; m >>= 1) {
                        v = add2(v, __shfl_xor_sync(0xffffffffu, v, m));
                        q = add2(q, __shfl_xor_sync(0xffffffffu, q, m));
                    }
                    if (lane == i) accS = add2(accS, v);
                    if (lane == 16 + i) accQ = add2(accQ, q);
                }
            }
        }

        if (STATS) {
            if (lane < 8) {
                float lo, hi;
                unpack2(lo, hi, accS);
                atomicAdd(osum + tb + 2 * lane, lo);
                atomicAdd(osum + tb + 2 * lane + 1, hi);
            }
            if (lane >= 16 && lane < 24) {
                float lo, hi;
                unpack2(lo, hi, accQ);
                atomicAdd(osq + tb + 2 * (lane - 16), lo);
                atomicAdd(osq + tb + 2 * (lane - 16) + 1, hi);
            }
        }
    }
}

// dual-problem wrapper: blockIdx.y selects the conv problem
template <int CIN, int COUT, bool AF1, bool CB1, bool ST1, bool AF2, bool CB2, bool ST2>
__global__ void __launch_bounds__(256)
fused_conv_dual(const float* in1, const float* in1b, const int* nbr1, const int* perm1, const int* hist1,
                const float* W1, const float* ps1a, const float* pq1a, const float* g1a, const float* b1a,
                const float* ps1b, const float* pq1b, const float* g1b, const float* b1b,
                float* out1, float* osum1, float* osq1,
                const float* in2, const float* in2b, const int* nbr2, const int* perm2, const int* hist2,
                const float* W2, const float* ps2a, const float* pq2a, const float* g2a, const float* b2a,
                const float* ps2b, const float* pq2b, const float* g2b, const float* b2b,
                float* out2, float* osum2, float* osq2,
                int n, int ntiles, int DB, int SBX) {
    extern __shared__ __align__(16) float sm[];
    if (blockIdx.y == 0)
        fused_conv_body<CIN, COUT, AF1, CB1, ST1>(sm, in1, in1b, nbr1, perm1, hist1, W1,
            ps1a, pq1a, g1a, b1a, ps1b, pq1b, g1b, b1b, out1, osum1, osq1, n, ntiles, DB, SBX);
    else
        fused_conv_body<CIN, COUT, AF2, CB2, ST2>(sm, in2, in2b, nbr2, perm2, hist2, W2,
            ps2a, pq2a, g2a, b2a, ps2b, pq2b, g2b, b2b, out2, osum2, osq2, n, ntiles, DB, SBX);
}

// ---------------- out = bnA(a) + bnB(b); bn from SUM/SQ in prologue --------
// Block 0 also zeroes hist/ctr for the NEXT call/replay — safe because no
// block of this kernel reads them, and the graph serializes replays.
template <int C>
__global__ void combine_kernel(const float* __restrict__ a,
                               const float* __restrict__ suma, const float* __restrict__ sqa,
                               const float* __restrict__ ga, const float* __restrict__ ba,
                               const float* __restrict__ bsrc,
                               const float* __restrict__ sumb, const float* __restrict__ sqb,
                               const float* __restrict__ gb, const float* __restrict__ bb,
                               float* __restrict__ o, int n,
                               int* __restrict__ hA, int* __restrict__ hB,
                               int* __restrict__ cA, int* __restrict__ cB) {
    if (blockIdx.x == 0) {
        for (int i = threadIdx.x; i < 512; i += blockDim.x) {
            hA[i] = 0; hB[i] = 0; cA[i] = 0; cB[i] = 0;
        }
    }
    __shared__ float sA[C], hAa[C], sB[C], hBb[C];
    const float inv_n = 1.0f / (float)n;
    for (int i = threadIdx.x; i < C; i += blockDim.x) {
        float m   = suma[i] * inv_n;
        float var = sqa[i] * inv_n - m * m;
        float s   = ga[i] / sqrtf(var + EPSV);
        sA[i] = s; hAa[i] = ba[i] - m * s;
        m   = sumb[i] * inv_n;
        var = sqb[i] * inv_n - m * m;
        s   = gb[i] / sqrtf(var + EPSV);
        sB[i] = s; hBb[i] = bb[i] - m * s;
    }
    __syncthreads();
    const int total = n * C;
    for (int i = blockIdx.x * blockDim.x + threadIdx.x; i < total; i += gridDim.x * blockDim.x) {
        int c = i & (C - 1);
        o[i] = fmaf(a[i], sA[c], hAa[c]) + fmaf(bsrc[i], sB[c], hBb[c]);
    }
}

// ---------------- host ----------------
static constexpr size_t smem_fused(int cin, int cout) {
    int mx = cin > cout ? cin : cout;
    size_t gemm = (size_t)(cin * (cout + 1) + 8 * 16 * (mx + 4) + 4 * cin) * sizeof(float);
    size_t sparse = (size_t)(9 * cin * 16 + 4 * cin) * sizeof(float);
    return gemm > sparse ? gemm : sparse;
}

extern "C" void kernel_launch(void* const* d_in, const int* in_sizes, int n_in,
                              void* d_out, int out_size) {
    const float* x      = (const float*)d_in[0];
    const int*   nbr133 = (const int*)  d_in[1];
    const int*   nbr313 = (const int*)  d_in[2];
    const float* W_c1   = (const float*)d_in[3];
    const float* g0     = (const float*)d_in[4];
    const float* b0     = (const float*)d_in[5];
    const float* W_c12  = (const float*)d_in[6];
    const float* g02    = (const float*)d_in[7];
    const float* b02    = (const float*)d_in[8];
    const float* W_c2   = (const float*)d_in[9];
    const float* W_c3   = (const float*)d_in[10];
    const float* g2     = (const float*)d_in[11];
    const float* b2     = (const float*)d_in[12];
    const float* W_r1   = (const float*)d_in[13];
    const float* rg0    = (const float*)d_in[14];
    const float* rb0    = (const float*)d_in[15];
    const float* W_r12  = (const float*)d_in[16];
    const float* rg02   = (const float*)d_in[17];
    const float* rb02   = (const float*)d_in[18];
    const float* W_r2   = (const float*)d_in[19];
    const float* rg1    = (const float*)d_in[20];
    const float* rb1    = (const float*)d_in[21];
    const float* W_r3   = (const float*)d_in[22];
    const float* rg2    = (const float*)d_in[23];
    const float* rb2    = (const float*)d_in[24];
    float* out = (float*)d_out;

    const int n = in_sizes[0] / 16;   // 120000

    float *BA, *BB, *BC, *BD, *BE, *SUM, *SQ;
    int *PA, *PB, *MA, *MB, *HA, *HB, *CA, *CB;
    cudaGetSymbolAddress((void**)&BA,  g_bufA);
    cudaGetSymbolAddress((void**)&BB,  g_bufB);
    cudaGetSymbolAddress((void**)&BC,  g_bufC);
    cudaGetSymbolAddress((void**)&BD,  g_bufD);
    cudaGetSymbolAddress((void**)&BE,  g_bufE);
    cudaGetSymbolAddress((void**)&SUM, g_sum);
    cudaGetSymbolAddress((void**)&SQ,  g_sq);
    cudaGetSymbolAddress((void**)&PA,  g_permA);
    cudaGetSymbolAddress((void**)&PB,  g_permB);
    cudaGetSymbolAddress((void**)&MA,  g_maskA);
    cudaGetSymbolAddress((void**)&MB,  g_maskB);
    cudaGetSymbolAddress((void**)&HA,  g_histA);
    cudaGetSymbolAddress((void**)&HB,  g_histB);
    cudaGetSymbolAddress((void**)&CA,  g_ctrA);
    cudaGetSymbolAddress((void**)&CB,  g_ctrB);

    static int inited = 0;
    if (!inited) {
        inited = 1;
        cudaFuncSetAttribute((const void*)fused_conv_dual<64, 64, true, false, true, true, false, true>,
                             cudaFuncAttributeMaxDynamicSharedMemorySize, (int)smem_fused(64, 64));
        cudaFuncSetAttribute((const void*)fused_conv_dual<32, 64, false, true, true, false, true, true>,
                             cudaFuncAttributeMaxDynamicSharedMemorySize, (int)smem_fused(32, 64));
    }

    const int TB = 256;
    const int ntiles = (n + TB - 1) / TB;
    const int G = ntiles;
    // grid shapes: nodes 3/4 keep R14's proven single-wave shape;
    // nodes 5/6 sized to exact smem-limited residency (5/SM and 4/SM).
    const int DB34  = 148, SBX34 = 64;    // 32-channel convs: (148+128)*2 = 552
    const int DB5   = 222, SBX5  = 37;    // 43.6KB -> 5/SM -> (222+148)*2 = 740
    const int DB6   = 148, SBX6  = 37;    // 52.5KB -> 4/SM -> (148+148)*2 = 592

    // ----- node 1: hist (+ zero SUM/SQ) -----
    mask_hist_kernel<<<dim3(G, 2), TB>>>(nbr133, nbr313, n, HA, HB, MA, MB, SUM, SQ);
    // ----- node 2: scatter (block-local scan) -----
    scatter_kernel<<<dim3((n + 511) / 512, 2), 512>>>(MA, MB, n, HA, HB, CA, CB, PA, PB);

    // ===== node 3: c1 (x,133 -> BA, stats SUM0) || c2 (x,313 -> BC) =====
    fused_conv_dual<16, 32, false, false, true, false, false, false>
        <<<dim3(DB34 + SBX34 * 2, 2), TB, smem_fused(16, 32)>>>(
        x, nullptr, nbr133, PA, HA, W_c1,
        nullptr, nullptr, nullptr, nullptr, nullptr, nullptr, nullptr, nullptr,
        BA, SUM + 0, SQ + 0,
        x, nullptr, nbr313, PB, HB, W_c2,
        nullptr, nullptr, nullptr, nullptr, nullptr, nullptr, nullptr, nullptr,
        BC, nullptr, nullptr,
        n, ntiles, DB34, SBX34);

    // ===== node 4: c12 (aff0(BA),313 -> BB, stats SUM64) || c3 (BC,133 -> BD, stats SUM128) =====
    fused_conv_dual<32, 32, true, false, true, false, false, true>
        <<<dim3(DB34 + SBX34 * 2, 2), TB, smem_fused(32, 32)>>>(
        BA, nullptr, nbr313, PB, HB, W_c12,
        SUM + 0, SQ + 0, g0, b0, nullptr, nullptr, nullptr, nullptr,
        BB, SUM + 64, SQ + 64,
        BC, nullptr, nbr133, PA, HA, W_c3,
        nullptr, nullptr, nullptr, nullptr, nullptr, nullptr, nullptr, nullptr,
        BD, SUM + 128, SQ + 128,
        n, ntiles, DB34, SBX34);

    // ===== node 5: y = bn2(BD)+bn1(BB) fused into r1/r2 gather =====
    fused_conv_dual<32, 64, false, true, true, false, true, true>
        <<<dim3(DB5 + SBX5 * 4, 2), TB, smem_fused(32, 64)>>>(
        BD, BB, nbr313, PB, HB, W_r1,
        SUM + 128, SQ + 128, g2, b2, SUM + 64, SQ + 64, g02, b02,
        BA, SUM + 192, SQ + 192,
        BD, BB, nbr133, PA, HA, W_r2,
        SUM + 128, SQ + 128, g2, b2, SUM + 64, SQ + 64, g02, b02,
        BE, SUM + 320, SQ + 320,
        n, ntiles, DB5, SBX5);

    // ===== node 6: r12 (aff3(BA),133 -> BB, stats SUM256) || r3 (aff5(BE),313 -> BD, stats SUM384) =====
    fused_conv_dual<64, 64, true, false, true, true, false, true>
        <<<dim3(DB6 + SBX6 * 4, 2), TB, smem_fused(64, 64)>>>(
        BA, nullptr, nbr133, PA, HA, W_r12,
        SUM + 192, SQ + 192, rg0, rb0, nullptr, nullptr, nullptr, nullptr,
        BB, SUM + 256, SQ + 256,
        BE, nullptr, nbr313, PB, HB, W_r3,
        SUM + 320, SQ + 320, rg1, rb1, nullptr, nullptr, nullptr, nullptr,
        BD, SUM + 384, SQ + 384,
        n, ntiles, DB6, SBX6);

    // ===== node 7: out = bn6(BD) + bn4(BB); zero hist/ctr for next replay =====
    combine_kernel<64><<<1184, 256>>>(BD, SUM + 384, SQ + 384, rg2, rb2,
                                      BB, SUM + 256, SQ + 256, rg02, rb02, out, n,
                                      HA, HB, CA, CB);
}